// round 11
// baseline (speedup 1.0000x reference)
#include <cuda_runtime.h>
#include <cuda_bf16.h>
#include <cuda_fp16.h>
#include <cstdint>

using bf16 = __nv_bfloat16;

#define B_ 8
#define N_ 1024
#define D_ 512
#define MLP_ 2048
#define ROWS_ (B_ * N_)
#define NEGBIG (-1e10f)
#define NINF __int_as_float(0xff800000)
#define QSCALE 0.18033688011112042f   // 0.125 * log2(e)

// ---------------- scratch ----------------
__device__ bf16  g_h[ROWS_ * D_];
__device__ bf16  g_qkv[ROWS_ * 3 * D_];
__device__ bf16  g_attn[ROWS_ * D_];
__device__ float g_x1[ROWS_ * D_];
__device__ __half g_h2h[ROWS_ * D_];
__device__ __half g_ffh[ROWS_ * MLP_];
__device__ uint32_t g_mbits[B_ * N_ * 32];
__device__ bf16  g_Wqkv[D_ * 3 * D_];
__device__ bf16  g_Wout[D_ * D_];
__device__ __half g_W1h[D_ * MLP_];
__device__ __half g_W2h[MLP_ * D_];

// ---------------- helpers ----------------
template<bool HALF>
__device__ __forceinline__ void mma16816(float* c, const uint32_t* a, uint32_t b0, uint32_t b1) {
    if (HALF)
        asm volatile("mma.sync.aligned.m16n8k16.row.col.f32.f16.f16.f32 "
                     "{%0,%1,%2,%3},{%4,%5,%6,%7},{%8,%9},{%0,%1,%2,%3};\n"
                     : "+f"(c[0]), "+f"(c[1]), "+f"(c[2]), "+f"(c[3])
                     : "r"(a[0]), "r"(a[1]), "r"(a[2]), "r"(a[3]), "r"(b0), "r"(b1));
    else
        asm volatile("mma.sync.aligned.m16n8k16.row.col.f32.bf16.bf16.f32 "
                     "{%0,%1,%2,%3},{%4,%5,%6,%7},{%8,%9},{%0,%1,%2,%3};\n"
                     : "+f"(c[0]), "+f"(c[1]), "+f"(c[2]), "+f"(c[3])
                     : "r"(a[0]), "r"(a[1]), "r"(a[2]), "r"(a[3]), "r"(b0), "r"(b1));
}
__device__ __forceinline__ void ldsm4(uint32_t* r, uint32_t a) {
    asm volatile("ldmatrix.sync.aligned.m8n8.x4.shared.b16 {%0,%1,%2,%3},[%4];"
                 : "=r"(r[0]), "=r"(r[1]), "=r"(r[2]), "=r"(r[3]) : "r"(a));
}
__device__ __forceinline__ void ldsm4t(uint32_t* r, uint32_t a) {
    asm volatile("ldmatrix.sync.aligned.m8n8.x4.trans.shared.b16 {%0,%1,%2,%3},[%4];"
                 : "=r"(r[0]), "=r"(r[1]), "=r"(r[2]), "=r"(r[3]) : "r"(a));
}
__device__ __forceinline__ uint32_t packbf(float x, float y) {
    __nv_bfloat162 t = __floats2bfloat162_rn(x, y);
    return *(uint32_t*)&t;
}
__device__ __forceinline__ void cp16(uint32_t s, const void* g) {
    asm volatile("cp.async.cg.shared.global [%0],[%1],16;\n" :: "r"(s), "l"(g));
}
__device__ __forceinline__ void cp4(uint32_t s, const void* g) {
    asm volatile("cp.async.ca.shared.global [%0],[%1],4;\n" :: "r"(s), "l"(g));
}
__device__ __forceinline__ void cpcommit() { asm volatile("cp.async.commit_group;\n"); }
__device__ __forceinline__ void cpwait0() { asm volatile("cp.async.wait_group 0;\n"); }
__device__ __forceinline__ void cpwait1() { asm volatile("cp.async.wait_group 1;\n"); }

// ---------------- fused weight convert ----------------
#define NW1 786432
#define NW2 262144
#define NW3 1048576
#define NW4 1048576
__global__ void cvtall_kernel(const float* __restrict__ wqkv, const float* __restrict__ wout,
                              const float* __restrict__ w1, const float* __restrict__ w2,
                              bf16* __restrict__ dqkv, bf16* __restrict__ dout,
                              __half* __restrict__ d1, __half* __restrict__ d2) {
    int i = blockIdx.x * blockDim.x + threadIdx.x;
    if (i < NW1) { dqkv[i] = __float2bfloat16(wqkv[i]); return; }
    i -= NW1;
    if (i < NW2) { dout[i] = __float2bfloat16(wout[i]); return; }
    i -= NW2;
    if (i < NW3) { d1[i] = __float2half_rn(w1[i]); return; }
    i -= NW3;
    if (i < NW4) { d2[i] = __float2half_rn(w2[i]); }
}

__global__ void maskbits_kernel(const float* __restrict__ mask, uint32_t* __restrict__ bits) {
    int idx = blockIdx.x * blockDim.x + threadIdx.x;
    uint32_t bal = __ballot_sync(0xffffffffu, mask[idx] == 1.0f);
    if ((idx & 31) == 0) bits[idx >> 5] = bal;
}

// ---------------- LayerNorm: warp-per-row, 8 rows/CTA. OUT: 0=bf16, 1=fp16 ------
template<int OUT>
__global__ void __launch_bounds__(256) ln_kernel(const float* __restrict__ x,
                                                 const float* __restrict__ gam,
                                                 const float* __restrict__ bet,
                                                 void* __restrict__ out) {
    int w = threadIdx.x >> 5, lane = threadIdx.x & 31;
    size_t row = (size_t)blockIdx.x * 8 + w;
    const float4* xr = (const float4*)(x + row * D_);
    float4 v[4];
    float s = 0.0f, sq = 0.0f;
    #pragma unroll
    for (int i = 0; i < 4; i++) {
        v[i] = xr[lane + i * 32];
        s  += v[i].x + v[i].y + v[i].z + v[i].w;
        sq += v[i].x * v[i].x + v[i].y * v[i].y + v[i].z * v[i].z + v[i].w * v[i].w;
    }
    #pragma unroll
    for (int o = 16; o > 0; o >>= 1) {
        s  += __shfl_xor_sync(0xffffffffu, s, o);
        sq += __shfl_xor_sync(0xffffffffu, sq, o);
    }
    float mu = s * (1.0f / D_);
    float rs = rsqrtf(sq * (1.0f / D_) - mu * mu + 1e-5f);
    #pragma unroll
    for (int i = 0; i < 4; i++) {
        int fi = lane + i * 32;
        float4 gv = ((const float4*)gam)[fi];
        float4 bv = ((const float4*)bet)[fi];
        float o0 = (v[i].x - mu) * rs * gv.x + bv.x;
        float o1 = (v[i].y - mu) * rs * gv.y + bv.y;
        float o2 = (v[i].z - mu) * rs * gv.z + bv.z;
        float o3 = (v[i].w - mu) * rs * gv.w + bv.w;
        if (OUT == 0) {
            bf16* o = (bf16*)out + row * D_ + fi * 4;
            ((__nv_bfloat162*)o)[0] = __floats2bfloat162_rn(o0, o1);
            ((__nv_bfloat162*)o)[1] = __floats2bfloat162_rn(o2, o3);
        } else {
            __half* o = (__half*)out + row * D_ + fi * 4;
            ((__half2*)o)[0] = __floats2half2_rn(o0, o1);
            ((__half2*)o)[1] = __floats2half2_rn(o2, o3);
        }
    }
}

// ---------------- flash attention (round-7 proven) ----------------
#define LQ 72
#define FL_SMEM (3 * 128 * LQ * 2 + 2 * 512 * 4)
__global__ void __launch_bounds__(256) flash_kernel(const bf16* __restrict__ qkv,
                                                    const uint32_t* __restrict__ mbits,
                                                    bf16* __restrict__ attn) {
    extern __shared__ char sm[];
    uint32_t sQ = (uint32_t)__cvta_generic_to_shared(sm);
    uint32_t sK = sQ + 128 * LQ * 2;
    uint32_t sV = sK + 128 * LQ * 2;
    uint32_t sM = sV + 128 * LQ * 2;
    uint32_t* mw = (uint32_t*)(sm + 3 * 128 * LQ * 2);

    int bh = blockIdx.y, b = bh >> 3, h = bh & 7;
    int tid = threadIdx.x, w = tid >> 5, lane = tid & 31, g = lane >> 2, tg = lane & 3;
    int q0 = blockIdx.x * 128;
    size_t base = (size_t)b * N_ * 1536;

    #pragma unroll
    for (int it = 0, c = tid; it < 4; it++, c += 256) {
        int r = c >> 3, d0 = (c & 7) * 8;
        cp16(sQ + (r * LQ + d0) * 2, qkv + base + (size_t)(q0 + r) * 1536 + h * 64 + d0);
        cp16(sK + (r * LQ + d0) * 2, qkv + base + (size_t)r * 1536 + 512 + h * 64 + d0);
    }
    #pragma unroll
    for (int it = 0, c = tid; it < 2; it++, c += 256)
        cp4(sM + c * 4, &mbits[((size_t)b * N_ + q0 + (c >> 2)) * 32 + (c & 3)]);
    cpcommit();

    float Oa[8][4];
    #pragma unroll
    for (int i = 0; i < 8; i++)
        #pragma unroll
        for (int j = 0; j < 4; j++) Oa[i][j] = 0.0f;
    float lrow0 = 0.0f, lrow1 = 0.0f;

    int aRow = w * 16 + ((lane >> 3) & 1) * 8 + (lane & 7);
    int aSel = (lane >> 4) * 8;
    int bRowOff = (lane >> 4) * 8 + (lane & 7);
    int bSel = ((lane >> 3) & 1) * 8;
    int vKeyOff = ((lane >> 3) & 1) * 8 + (lane & 7);
    int vDSel = (lane >> 4);

    cpwait0();
    __syncthreads();

    for (int kt = 0; kt < 8; kt++) {
        int cur = kt & 1;
        #pragma unroll
        for (int it = 0, c = tid; it < 4; it++, c += 256) {
            int r = c >> 3, d0 = (c & 7) * 8;
            cp16(sV + (r * LQ + d0) * 2,
                 qkv + base + (size_t)(kt * 128 + r) * 1536 + 1024 + h * 64 + d0);
        }
        cpcommit();

        float sacc[16][4];
        #pragma unroll
        for (int nf = 0; nf < 16; nf++)
            #pragma unroll
            for (int j = 0; j < 4; j++) sacc[nf][j] = 0.0f;
        #pragma unroll
        for (int kk = 0; kk < 64; kk += 16) {
            uint32_t aq[4];
            ldsm4(aq, sQ + (uint32_t)(aRow * LQ + kk + aSel) * 2);
            #pragma unroll
            for (int nfp = 0; nfp < 8; nfp++) {
                uint32_t bq[4];
                ldsm4(bq, sK + (uint32_t)((nfp * 16 + bRowOff) * LQ + kk + bSel) * 2);
                mma16816<false>(sacc[2 * nfp], aq, bq[0], bq[1]);
                mma16816<false>(sacc[2 * nfp + 1], aq, bq[2], bq[3]);
            }
        }

        int r0l = w * 16 + g;
        uint32_t mwa[4], mwb[4];
        #pragma unroll
        for (int i = 0; i < 4; i++) {
            mwa[i] = mw[cur * 512 + r0l * 4 + i];
            mwb[i] = mw[cur * 512 + (r0l + 8) * 4 + i];
        }
        float rs0 = 0.0f, rs1 = 0.0f;
        #pragma unroll
        for (int nf = 0; nf < 16; nf++) {
            int c0 = nf * 8 + 2 * tg;
            uint32_t wa = mwa[c0 >> 5], wb = mwb[c0 >> 5];
            int shm = c0 & 31;
            float p00 = ((wa >> shm) & 1)       ? 0.0f : exp2f(sacc[nf][0]);
            float p01 = ((wa >> (shm + 1)) & 1) ? 0.0f : exp2f(sacc[nf][1]);
            float p10 = ((wb >> shm) & 1)       ? 0.0f : exp2f(sacc[nf][2]);
            float p11 = ((wb >> (shm + 1)) & 1) ? 0.0f : exp2f(sacc[nf][3]);
            sacc[nf][0] = p00; sacc[nf][1] = p01; sacc[nf][2] = p10; sacc[nf][3] = p11;
            rs0 += p00 + p01; rs1 += p10 + p11;
        }
        rs0 += __shfl_xor_sync(0xffffffffu, rs0, 1);
        rs0 += __shfl_xor_sync(0xffffffffu, rs0, 2);
        rs1 += __shfl_xor_sync(0xffffffffu, rs1, 1);
        rs1 += __shfl_xor_sync(0xffffffffu, rs1, 2);
        lrow0 += rs0;
        lrow1 += rs1;
        uint32_t pa[8][4];
        #pragma unroll
        for (int f = 0; f < 8; f++) {
            pa[f][0] = packbf(sacc[2 * f][0], sacc[2 * f][1]);
            pa[f][1] = packbf(sacc[2 * f][2], sacc[2 * f][3]);
            pa[f][2] = packbf(sacc[2 * f + 1][0], sacc[2 * f + 1][1]);
            pa[f][3] = packbf(sacc[2 * f + 1][2], sacc[2 * f + 1][3]);
        }
        __syncthreads();

        bool more = kt < 7;
        if (more) {
            #pragma unroll
            for (int it = 0, c = tid; it < 4; it++, c += 256) {
                int r = c >> 3, d0 = (c & 7) * 8;
                cp16(sK + (r * LQ + d0) * 2,
                     qkv + base + (size_t)((kt + 1) * 128 + r) * 1536 + 512 + h * 64 + d0);
            }
            #pragma unroll
            for (int it = 0, c = tid; it < 2; it++, c += 256)
                cp4(sM + ((cur ^ 1) * 512 + c) * 4,
                    &mbits[((size_t)b * N_ + q0 + (c >> 2)) * 32 + (kt + 1) * 4 + (c & 3)]);
            cpcommit();
            cpwait1();
        } else {
            cpwait0();
        }
        __syncthreads();

        #pragma unroll
        for (int f = 0; f < 8; f++) {
            #pragma unroll
            for (int q = 0; q < 4; q++) {
                uint32_t bv[4];
                ldsm4t(bv, sV + (uint32_t)((f * 16 + vKeyOff) * LQ + (vDSel + 2 * q) * 8) * 2);
                mma16816<false>(Oa[2 * q], pa[f], bv[0], bv[1]);
                mma16816<false>(Oa[2 * q + 1], pa[f], bv[2], bv[3]);
            }
        }
        cpwait0();
        __syncthreads();
    }

    float inv0 = 1.0f / lrow0, inv1 = 1.0f / lrow1;
    int orow = b * N_ + q0 + w * 16 + g;
    #pragma unroll
    for (int df = 0; df < 8; df++) {
        int col = h * 64 + df * 8 + 2 * tg;
        *(__nv_bfloat162*)(attn + (size_t)orow * 512 + col) =
            __floats2bfloat162_rn(Oa[df][0] * inv0, Oa[df][1] * inv0);
        *(__nv_bfloat162*)(attn + (size_t)(orow + 8) * 512 + col) =
            __floats2bfloat162_rn(Oa[df][2] * inv1, Oa[df][3] * inv1);
    }
}

// ---------------- fused att_topk + prune ----------------
__device__ __forceinline__ float blkmax(float v, float* red, int tid) {
    #pragma unroll
    for (int o = 16; o > 0; o >>= 1) v = fmaxf(v, __shfl_xor_sync(0xffffffffu, v, o));
    if ((tid & 31) == 0) red[tid >> 5] = v;
    __syncthreads();
    if (tid < 32) {
        float t = red[tid];
        #pragma unroll
        for (int o = 16; o > 0; o >>= 1) t = fmaxf(t, __shfl_xor_sync(0xffffffffu, t, o));
        if (tid == 0) red[0] = t;
    }
    __syncthreads();
    float r = red[0];
    __syncthreads();
    return r;
}
__device__ __forceinline__ float blksum(float v, float* red, int tid) {
    #pragma unroll
    for (int o = 16; o > 0; o >>= 1) v += __shfl_xor_sync(0xffffffffu, v, o);
    if ((tid & 31) == 0) red[tid >> 5] = v;
    __syncthreads();
    if (tid < 32) {
        float t = red[tid];
        #pragma unroll
        for (int o = 16; o > 0; o >>= 1) t += __shfl_xor_sync(0xffffffffu, t, o);
        if (tid == 0) red[0] = t;
    }
    __syncthreads();
    float r = red[0];
    __syncthreads();
    return r;
}
__global__ void __launch_bounds__(1024) topkprune_kernel(const bf16* __restrict__ qkv,
                                                         const float* __restrict__ mask,
                                                         float* __restrict__ out) {
    int b = blockIdx.x, m = threadIdx.x;
    __shared__ float q0s[512];
    __shared__ float red[32];
    __shared__ float key[N_];
    size_t rb = (size_t)b * N_ * 1536;
    if (m < 512) q0s[m] = __bfloat162float(qkv[rb + m]);
    __syncthreads();
    const bf16* krow = qkv + rb + (size_t)m * 1536 + 512;
    float s[8];
    #pragma unroll
    for (int h = 0; h < 8; h++) {
        float acc = 0.0f;
        #pragma unroll
        for (int j = 0; j < 64; j += 8) {
            uint4 kv = *(const uint4*)(krow + h * 64 + j);
            bf16 t[8]; *(uint4*)t = kv;
            #pragma unroll
            for (int i = 0; i < 8; i++) acc += q0s[h * 64 + j + i] * __bfloat162float(t[i]);
        }
        s[h] = acc;                       // log2 domain (Q pre-scaled)
    }
    if (mask[(size_t)b * N_ * N_ + m] == 1.0f)
        #pragma unroll
        for (int h = 0; h < 8; h++) s[h] = NEGBIG;
    float val = 0.0f;
    #pragma unroll
    for (int h = 0; h < 8; h++) {
        float M = blkmax(s[h], red, m);
        float p = exp2f(s[h] - M);
        float L = blksum(p, red, m);
        val += p / L;
    }
    val *= 0.125f;
    float km = (m == 0) ? NINF : val;
    key[m] = km;
    __syncthreads();
    int rank = 0;
    for (int j = 0; j < N_; j++) {
        float kj = key[j];
        rank += (kj > km) || (kj == km && j < m);
    }
    if (rank >= 959 && rank < 1023) out[4194304 + b * 64 + (rank - 959)] = (float)m;
    if (m == 0) out[4194816 + b] = -1.0f;
    if (m < 16) out[4194824 + b * 16 + m] = 0.0f;
}

// ------- 16-bit GEMM, cp.async 2-stage, tile 128x64, 3 CTAs/SM target -------
// EPI: 0 = store 16-bit (cols<qcols scaled); 2 = +bias+resid->fp32; 3 = gelu->16-bit
template<int EPI, bool HALF>
__global__ void __launch_bounds__(256, 3) gemm_k(
    const uint16_t* __restrict__ A, const uint16_t* __restrict__ Bm, void* __restrict__ Cp,
    int K, int lda, int ldb, int ldc,
    const float* __restrict__ bias, const float* __restrict__ resid,
    int qcols, float qscale)
{
    constexpr int LA = 40, LB = 72;
    __shared__ uint16_t As[2][128 * LA];
    __shared__ uint16_t Bs[2][32 * LB];
    int tid = threadIdx.x, warp = tid >> 5, lane = tid & 31;
    int g = lane >> 2, tg = lane & 3;
    int warpM = warp & 3, warpN = warp >> 2;     // 4 x 2
    int row0 = blockIdx.y * 128, col0 = blockIdx.x * 64;
    uint32_t sA = (uint32_t)__cvta_generic_to_shared(As);
    uint32_t sB = (uint32_t)__cvta_generic_to_shared(Bs);
    int koff = ((lane >> 3) & 1) * 8 + (lane & 7);
    int nsel = (lane >> 4) * 8;

    float acc[2][4][4];
    #pragma unroll
    for (int a = 0; a < 2; a++)
        #pragma unroll
        for (int b2 = 0; b2 < 4; b2++)
            #pragma unroll
            for (int c = 0; c < 4; c++) acc[a][b2][c] = 0.0f;

    auto issue = [&](int st, int k0) {
        #pragma unroll
        for (int it = 0, c = tid; it < 2; it++, c += 256) {
            int r = c >> 2, kc = (c & 3) * 8;
            cp16(sA + (st * 128 * LA + r * LA + kc) * 2,
                 A + (size_t)(row0 + r) * lda + k0 + kc);
        }
        {
            int c = tid;
            int kk = c >> 3, nc = (c & 7) * 8;
            cp16(sB + (st * 32 * LB + kk * LB + nc) * 2,
                 Bm + (size_t)(k0 + kk) * ldb + col0 + nc);
        }
        cpcommit();
    };

    issue(0, 0);
    int nk = K / 32;
    for (int i = 0; i < nk; i++) {
        int st = i & 1;
        cpwait0();
        __syncthreads();
        if (i + 1 < nk) issue(st ^ 1, (i + 1) * 32);
        const uint16_t* Ab = As[st];
        uint32_t sBst = sB + st * 32 * LB * 2;
        #pragma unroll
        for (int kk = 0; kk < 32; kk += 16) {
            uint32_t af[2][4];
            #pragma unroll
            for (int mt = 0; mt < 2; mt++) {
                const uint16_t* p = &Ab[(warpM * 32 + mt * 16 + g) * LA + kk + 2 * tg];
                af[mt][0] = *(const uint32_t*)p;
                af[mt][1] = *(const uint32_t*)(p + 8 * LA);
                af[mt][2] = *(const uint32_t*)(p + 8);
                af[mt][3] = *(const uint32_t*)(p + 8 * LA + 8);
            }
            #pragma unroll
            for (int p2 = 0; p2 < 2; p2++) {
                uint32_t bq[4];
                ldsm4t(bq, sBst + (uint32_t)((kk + koff) * LB + warpN * 32 + p2 * 16 + nsel) * 2);
                #pragma unroll
                for (int mt = 0; mt < 2; mt++) {
                    mma16816<HALF>(acc[mt][2 * p2], af[mt], bq[0], bq[1]);
                    mma16816<HALF>(acc[mt][2 * p2 + 1], af[mt], bq[2], bq[3]);
                }
            }
        }
        __syncthreads();
    }
    #pragma unroll
    for (int mt = 0; mt < 2; mt++)
        #pragma unroll
        for (int nt = 0; nt < 4; nt++) {
            int r = row0 + warpM * 32 + mt * 16 + g;
            int cc = col0 + warpN * 32 + nt * 8 + 2 * tg;
            #pragma unroll
            for (int hf = 0; hf < 2; hf++) {
                int rr = r + hf * 8;
                float v0 = acc[mt][nt][hf * 2], v1 = acc[mt][nt][hf * 2 + 1];
                long idx = (long)rr * ldc + cc;
                if (EPI == 2) {
                    v0 += bias[cc] + resid[idx];
                    v1 += bias[cc + 1] + resid[idx + 1];
                    *(float2*)((float*)Cp + idx) = make_float2(v0, v1);
                } else {
                    if (EPI == 3) {
                        v0 += bias[cc]; v1 += bias[cc + 1];
                        v0 = 0.5f * v0 * (1.0f + erff(v0 * 0.70710678f));
                        v1 = 0.5f * v1 * (1.0f + erff(v1 * 0.70710678f));
                    }
                    if (EPI == 0 && cc < qcols) { v0 *= qscale; v1 *= qscale; }
                    uint32_t pk;
                    if (HALF) { __half2 t = __floats2half2_rn(v0, v1); pk = *(uint32_t*)&t; }
                    else pk = packbf(v0, v1);
                    *(uint32_t*)((uint16_t*)Cp + idx) = pk;
                }
            }
        }
}

// ---------------- host ----------------
template <typename T>
static T* symaddr(const T& sym) {
    void* p = nullptr;
    cudaGetSymbolAddress(&p, sym);
    return (T*)p;
}

extern "C" void kernel_launch(void* const* d_in, const int* in_sizes, int n_in,
                              void* d_out, int out_size) {
    const float* x    = (const float*)d_in[0];
    const float* mask = (const float*)d_in[1];
    const float* Wqkv = (const float*)d_in[2];
    const float* Wout = (const float*)d_in[3];
    const float* bout = (const float*)d_in[4];
    const float* ln1g = (const float*)d_in[5];
    const float* ln1b = (const float*)d_in[6];
    const float* ln2g = (const float*)d_in[7];
    const float* ln2b = (const float*)d_in[8];
    const float* W1   = (const float*)d_in[9];
    const float* b1   = (const float*)d_in[10];
    const float* W2   = (const float*)d_in[11];
    const float* b2   = (const float*)d_in[12];

    bf16* h = (bf16*)symaddr(g_h);
    bf16* qkv = (bf16*)symaddr(g_qkv);
    bf16* attn = (bf16*)symaddr(g_attn);
    float* x1 = (float*)symaddr(g_x1);
    __half* h2h = (__half*)symaddr(g_h2h);
    __half* ffh = (__half*)symaddr(g_ffh);
    uint32_t* mb = (uint32_t*)symaddr(g_mbits);
    bf16* wqkv = (bf16*)symaddr(g_Wqkv);
    bf16* wout = (bf16*)symaddr(g_Wout);
    __half* w1h = (__half*)symaddr(g_W1h);
    __half* w2h = (__half*)symaddr(g_W2h);

    cudaFuncSetAttribute(flash_kernel, cudaFuncAttributeMaxDynamicSharedMemorySize, FL_SMEM);

    cvtall_kernel<<<(NW1 + NW2 + NW3 + NW4 + 255) / 256, 256>>>(
        Wqkv, Wout, W1, W2, wqkv, wout, w1h, w2h);
    maskbits_kernel<<<B_ * N_ * N_ / 256, 256>>>(mask, mb);
    ln_kernel<0><<<ROWS_ / 8, 256>>>(x, ln1g, ln1b, h);

    // qkv = h @ Wqkv  (bf16; Q cols pre-scaled by 0.125*log2e)
    gemm_k<0, false><<<dim3(24, 64), 256>>>(
        (const uint16_t*)h, (const uint16_t*)wqkv, qkv, D_, D_, 3 * D_, 3 * D_,
        nullptr, nullptr, 512, QSCALE);
    flash_kernel<<<dim3(8, 64), 256, FL_SMEM>>>(qkv, mb, attn);
    topkprune_kernel<<<B_, 1024>>>(qkv, mask, (float*)d_out);
    // x1 = x + attn @ Wout + bout  (bf16)
    gemm_k<2, false><<<dim3(8, 64), 256>>>(
        (const uint16_t*)attn, (const uint16_t*)wout, x1, D_, D_, D_, D_,
        bout, x, 0, 1.0f);
    ln_kernel<1><<<ROWS_ / 8, 256>>>(x1, ln2g, ln2b, h2h);
    // ff = gelu(h2 @ W1 + b1)  (fp16)
    gemm_k<3, true><<<dim3(32, 64), 256>>>(
        (const uint16_t*)h2h, (const uint16_t*)w1h, ffh, D_, D_, MLP_, MLP_,
        b1, nullptr, 0, 1.0f);
    // out = x1 + ff @ W2 + b2  (fp16)
    gemm_k<2, true><<<dim3(8, 64), 256>>>(
        (const uint16_t*)ffh, (const uint16_t*)w2h, (float*)d_out, MLP_, MLP_, D_, D_,
        b2, x1, 0, 1.0f);
}

// round 12
// speedup vs baseline: 1.1556x; 1.1556x over previous
#include <cuda_runtime.h>
#include <cuda_bf16.h>
#include <cuda_fp16.h>
#include <cstdint>

using bf16 = __nv_bfloat16;

#define B_ 8
#define N_ 1024
#define D_ 512
#define MLP_ 2048
#define ROWS_ (B_ * N_)
#define NEGBIG (-1e10f)
#define NINF __int_as_float(0xff800000)

// ---------------- scratch ----------------
__device__ bf16  g_h[ROWS_ * D_];
__device__ bf16  g_qkv[ROWS_ * 3 * D_];
__device__ bf16  g_attn[ROWS_ * D_];
__device__ float g_x1[ROWS_ * D_];
__device__ __half g_h2h[ROWS_ * D_];
__device__ __half g_ffh[ROWS_ * MLP_];
__device__ float g_topk[B_ * N_];
__device__ uint32_t g_mbits[B_ * N_ * 32];
__device__ bf16  g_Wqkv[D_ * 3 * D_];
__device__ bf16  g_Wout[D_ * D_];
__device__ __half g_W1h[D_ * MLP_];
__device__ __half g_W2h[MLP_ * D_];

// ---------------- helpers ----------------
template<bool HALF>
__device__ __forceinline__ void mma16816(float* c, const uint32_t* a, uint32_t b0, uint32_t b1) {
    if (HALF)
        asm volatile("mma.sync.aligned.m16n8k16.row.col.f32.f16.f16.f32 "
                     "{%0,%1,%2,%3},{%4,%5,%6,%7},{%8,%9},{%0,%1,%2,%3};\n"
                     : "+f"(c[0]), "+f"(c[1]), "+f"(c[2]), "+f"(c[3])
                     : "r"(a[0]), "r"(a[1]), "r"(a[2]), "r"(a[3]), "r"(b0), "r"(b1));
    else
        asm volatile("mma.sync.aligned.m16n8k16.row.col.f32.bf16.bf16.f32 "
                     "{%0,%1,%2,%3},{%4,%5,%6,%7},{%8,%9},{%0,%1,%2,%3};\n"
                     : "+f"(c[0]), "+f"(c[1]), "+f"(c[2]), "+f"(c[3])
                     : "r"(a[0]), "r"(a[1]), "r"(a[2]), "r"(a[3]), "r"(b0), "r"(b1));
}
__device__ __forceinline__ void ldsm4(uint32_t* r, uint32_t a) {
    asm volatile("ldmatrix.sync.aligned.m8n8.x4.shared.b16 {%0,%1,%2,%3},[%4];"
                 : "=r"(r[0]), "=r"(r[1]), "=r"(r[2]), "=r"(r[3]) : "r"(a));
}
__device__ __forceinline__ void ldsm4t(uint32_t* r, uint32_t a) {
    asm volatile("ldmatrix.sync.aligned.m8n8.x4.trans.shared.b16 {%0,%1,%2,%3},[%4];"
                 : "=r"(r[0]), "=r"(r[1]), "=r"(r[2]), "=r"(r[3]) : "r"(a));
}
__device__ __forceinline__ uint32_t packbf(float x, float y) {
    __nv_bfloat162 t = __floats2bfloat162_rn(x, y);
    return *(uint32_t*)&t;
}
__device__ __forceinline__ void cp16(uint32_t s, const void* g) {
    asm volatile("cp.async.cg.shared.global [%0],[%1],16;\n" :: "r"(s), "l"(g));
}
__device__ __forceinline__ void cp4(uint32_t s, const void* g) {
    asm volatile("cp.async.ca.shared.global [%0],[%1],4;\n" :: "r"(s), "l"(g));
}
__device__ __forceinline__ void cpcommit() { asm volatile("cp.async.commit_group;\n"); }
__device__ __forceinline__ void cpwait0() { asm volatile("cp.async.wait_group 0;\n"); }
__device__ __forceinline__ void cpwait1() { asm volatile("cp.async.wait_group 1;\n"); }

// ---------------- fused weight convert ----------------
#define NW1 786432
#define NW2 262144
#define NW3 1048576
#define NW4 1048576
__global__ void cvtall_kernel(const float* __restrict__ wqkv, const float* __restrict__ wout,
                              const float* __restrict__ w1, const float* __restrict__ w2,
                              bf16* __restrict__ dqkv, bf16* __restrict__ dout,
                              __half* __restrict__ d1, __half* __restrict__ d2) {
    int i = blockIdx.x * blockDim.x + threadIdx.x;
    if (i < NW1) { dqkv[i] = __float2bfloat16(wqkv[i]); return; }
    i -= NW1;
    if (i < NW2) { dout[i] = __float2bfloat16(wout[i]); return; }
    i -= NW2;
    if (i < NW3) { d1[i] = __float2half_rn(w1[i]); return; }
    i -= NW3;
    if (i < NW4) { d2[i] = __float2half_rn(w2[i]); }
}

__global__ void maskbits_kernel(const float* __restrict__ mask, uint32_t* __restrict__ bits) {
    int idx = blockIdx.x * blockDim.x + threadIdx.x;
    uint32_t bal = __ballot_sync(0xffffffffu, mask[idx] == 1.0f);
    if ((idx & 31) == 0) bits[idx >> 5] = bal;
}

// ---------------- LayerNorm: warp-per-row, 8 rows/CTA. OUT: 0=bf16, 1=fp16 ------
template<int OUT>
__global__ void __launch_bounds__(256) ln_kernel(const float* __restrict__ x,
                                                 const float* __restrict__ gam,
                                                 const float* __restrict__ bet,
                                                 void* __restrict__ out) {
    int w = threadIdx.x >> 5, lane = threadIdx.x & 31;
    size_t row = (size_t)blockIdx.x * 8 + w;
    const float4* xr = (const float4*)(x + row * D_);
    float4 v[4];
    float s = 0.0f, sq = 0.0f;
    #pragma unroll
    for (int i = 0; i < 4; i++) {
        v[i] = xr[lane + i * 32];
        s  += v[i].x + v[i].y + v[i].z + v[i].w;
        sq += v[i].x * v[i].x + v[i].y * v[i].y + v[i].z * v[i].z + v[i].w * v[i].w;
    }
    #pragma unroll
    for (int o = 16; o > 0; o >>= 1) {
        s  += __shfl_xor_sync(0xffffffffu, s, o);
        sq += __shfl_xor_sync(0xffffffffu, sq, o);
    }
    float mu = s * (1.0f / D_);
    float rs = rsqrtf(sq * (1.0f / D_) - mu * mu + 1e-5f);
    #pragma unroll
    for (int i = 0; i < 4; i++) {
        int fi = lane + i * 32;
        float4 gv = ((const float4*)gam)[fi];
        float4 bv = ((const float4*)bet)[fi];
        float o0 = (v[i].x - mu) * rs * gv.x + bv.x;
        float o1 = (v[i].y - mu) * rs * gv.y + bv.y;
        float o2 = (v[i].z - mu) * rs * gv.z + bv.z;
        float o3 = (v[i].w - mu) * rs * gv.w + bv.w;
        if (OUT == 0) {
            bf16* o = (bf16*)out + row * D_ + fi * 4;
            ((__nv_bfloat162*)o)[0] = __floats2bfloat162_rn(o0, o1);
            ((__nv_bfloat162*)o)[1] = __floats2bfloat162_rn(o2, o3);
        } else {
            __half* o = (__half*)out + row * D_ + fi * 4;
            ((__half2*)o)[0] = __floats2half2_rn(o0, o1);
            ((__half2*)o)[1] = __floats2half2_rn(o2, o3);
        }
    }
}

// ---------------- flash attention (round-6 proven: expf + online max) -----------
#define LQ 72
#define FL_SMEM (3 * 128 * LQ * 2 + 2 * 512 * 4)
__global__ void __launch_bounds__(256) flash_kernel(const bf16* __restrict__ qkv,
                                                    const uint32_t* __restrict__ mbits,
                                                    bf16* __restrict__ attn) {
    extern __shared__ char sm[];
    uint32_t sQ = (uint32_t)__cvta_generic_to_shared(sm);
    uint32_t sK = sQ + 128 * LQ * 2;
    uint32_t sV = sK + 128 * LQ * 2;
    uint32_t sM = sV + 128 * LQ * 2;
    uint32_t* mw = (uint32_t*)(sm + 3 * 128 * LQ * 2);

    int bh = blockIdx.y, b = bh >> 3, h = bh & 7;
    int tid = threadIdx.x, w = tid >> 5, lane = tid & 31, g = lane >> 2, tg = lane & 3;
    int q0 = blockIdx.x * 128;
    size_t base = (size_t)b * N_ * 1536;

    #pragma unroll
    for (int it = 0, c = tid; it < 4; it++, c += 256) {
        int r = c >> 3, d0 = (c & 7) * 8;
        cp16(sQ + (r * LQ + d0) * 2, qkv + base + (size_t)(q0 + r) * 1536 + h * 64 + d0);
        cp16(sK + (r * LQ + d0) * 2, qkv + base + (size_t)r * 1536 + 512 + h * 64 + d0);
    }
    #pragma unroll
    for (int it = 0, c = tid; it < 2; it++, c += 256)
        cp4(sM + c * 4, &mbits[((size_t)b * N_ + q0 + (c >> 2)) * 32 + (c & 3)]);
    cpcommit();

    float Oa[8][4];
    #pragma unroll
    for (int i = 0; i < 8; i++)
        #pragma unroll
        for (int j = 0; j < 4; j++) Oa[i][j] = 0.0f;
    float mrow0 = NINF, mrow1 = NINF, lrow0 = 0.0f, lrow1 = 0.0f;

    int aRow = w * 16 + ((lane >> 3) & 1) * 8 + (lane & 7);
    int aSel = (lane >> 4) * 8;
    int bRowOff = (lane >> 4) * 8 + (lane & 7);
    int bSel = ((lane >> 3) & 1) * 8;
    int vKeyOff = ((lane >> 3) & 1) * 8 + (lane & 7);
    int vDSel = (lane >> 4);

    cpwait0();
    __syncthreads();

    for (int kt = 0; kt < 8; kt++) {
        int cur = kt & 1;
        #pragma unroll
        for (int it = 0, c = tid; it < 4; it++, c += 256) {
            int r = c >> 3, d0 = (c & 7) * 8;
            cp16(sV + (r * LQ + d0) * 2,
                 qkv + base + (size_t)(kt * 128 + r) * 1536 + 1024 + h * 64 + d0);
        }
        cpcommit();

        float sacc[16][4];
        #pragma unroll
        for (int nf = 0; nf < 16; nf++)
            #pragma unroll
            for (int j = 0; j < 4; j++) sacc[nf][j] = 0.0f;
        #pragma unroll
        for (int kk = 0; kk < 64; kk += 16) {
            uint32_t aq[4];
            ldsm4(aq, sQ + (uint32_t)(aRow * LQ + kk + aSel) * 2);
            #pragma unroll
            for (int nfp = 0; nfp < 8; nfp++) {
                uint32_t bq[4];
                ldsm4(bq, sK + (uint32_t)((nfp * 16 + bRowOff) * LQ + kk + bSel) * 2);
                mma16816<false>(sacc[2 * nfp], aq, bq[0], bq[1]);
                mma16816<false>(sacc[2 * nfp + 1], aq, bq[2], bq[3]);
            }
        }

        int r0l = w * 16 + g;
        uint32_t mwa[4], mwb[4];
        #pragma unroll
        for (int i = 0; i < 4; i++) {
            mwa[i] = mw[cur * 512 + r0l * 4 + i];
            mwb[i] = mw[cur * 512 + (r0l + 8) * 4 + i];
        }
        float mx0 = -3e38f, mx1 = -3e38f;
        #pragma unroll
        for (int nf = 0; nf < 16; nf++) {
            int c0 = nf * 8 + 2 * tg;
            uint32_t wa = mwa[c0 >> 5], wb = mwb[c0 >> 5];
            int shm = c0 & 31;
            float s00 = ((wa >> shm) & 1) ? NEGBIG : sacc[nf][0] * 0.125f;
            float s01 = ((wa >> (shm + 1)) & 1) ? NEGBIG : sacc[nf][1] * 0.125f;
            float s10 = ((wb >> shm) & 1) ? NEGBIG : sacc[nf][2] * 0.125f;
            float s11 = ((wb >> (shm + 1)) & 1) ? NEGBIG : sacc[nf][3] * 0.125f;
            sacc[nf][0] = s00; sacc[nf][1] = s01; sacc[nf][2] = s10; sacc[nf][3] = s11;
            mx0 = fmaxf(mx0, fmaxf(s00, s01));
            mx1 = fmaxf(mx1, fmaxf(s10, s11));
        }
        mx0 = fmaxf(mx0, __shfl_xor_sync(0xffffffffu, mx0, 1));
        mx0 = fmaxf(mx0, __shfl_xor_sync(0xffffffffu, mx0, 2));
        mx1 = fmaxf(mx1, __shfl_xor_sync(0xffffffffu, mx1, 1));
        mx1 = fmaxf(mx1, __shfl_xor_sync(0xffffffffu, mx1, 2));
        float mn0 = fmaxf(mrow0, mx0), mn1 = fmaxf(mrow1, mx1);
        float cf0 = __expf(mrow0 - mn0), cf1 = __expf(mrow1 - mn1);
        mrow0 = mn0; mrow1 = mn1;
        float rs0 = 0.0f, rs1 = 0.0f;
        #pragma unroll
        for (int nf = 0; nf < 16; nf++) {
            float p00 = __expf(sacc[nf][0] - mn0);
            float p01 = __expf(sacc[nf][1] - mn0);
            float p10 = __expf(sacc[nf][2] - mn1);
            float p11 = __expf(sacc[nf][3] - mn1);
            sacc[nf][0] = p00; sacc[nf][1] = p01; sacc[nf][2] = p10; sacc[nf][3] = p11;
            rs0 += p00 + p01; rs1 += p10 + p11;
        }
        rs0 += __shfl_xor_sync(0xffffffffu, rs0, 1);
        rs0 += __shfl_xor_sync(0xffffffffu, rs0, 2);
        rs1 += __shfl_xor_sync(0xffffffffu, rs1, 1);
        rs1 += __shfl_xor_sync(0xffffffffu, rs1, 2);
        lrow0 = lrow0 * cf0 + rs0;
        lrow1 = lrow1 * cf1 + rs1;
        #pragma unroll
        for (int df = 0; df < 8; df++) {
            Oa[df][0] *= cf0; Oa[df][1] *= cf0;
            Oa[df][2] *= cf1; Oa[df][3] *= cf1;
        }
        uint32_t pa[8][4];
        #pragma unroll
        for (int f = 0; f < 8; f++) {
            pa[f][0] = packbf(sacc[2 * f][0], sacc[2 * f][1]);
            pa[f][1] = packbf(sacc[2 * f][2], sacc[2 * f][3]);
            pa[f][2] = packbf(sacc[2 * f + 1][0], sacc[2 * f + 1][1]);
            pa[f][3] = packbf(sacc[2 * f + 1][2], sacc[2 * f + 1][3]);
        }
        __syncthreads();

        bool more = kt < 7;
        if (more) {
            #pragma unroll
            for (int it = 0, c = tid; it < 4; it++, c += 256) {
                int r = c >> 3, d0 = (c & 7) * 8;
                cp16(sK + (r * LQ + d0) * 2,
                     qkv + base + (size_t)((kt + 1) * 128 + r) * 1536 + 512 + h * 64 + d0);
            }
            #pragma unroll
            for (int it = 0, c = tid; it < 2; it++, c += 256)
                cp4(sM + ((cur ^ 1) * 512 + c) * 4,
                    &mbits[((size_t)b * N_ + q0 + (c >> 2)) * 32 + (kt + 1) * 4 + (c & 3)]);
            cpcommit();
            cpwait1();
        } else {
            cpwait0();
        }
        __syncthreads();

        #pragma unroll
        for (int f = 0; f < 8; f++) {
            #pragma unroll
            for (int q = 0; q < 4; q++) {
                uint32_t bv[4];
                ldsm4t(bv, sV + (uint32_t)((f * 16 + vKeyOff) * LQ + (vDSel + 2 * q) * 8) * 2);
                mma16816<false>(Oa[2 * q], pa[f], bv[0], bv[1]);
                mma16816<false>(Oa[2 * q + 1], pa[f], bv[2], bv[3]);
            }
        }
        cpwait0();
        __syncthreads();
    }

    float inv0 = 1.0f / lrow0, inv1 = 1.0f / lrow1;
    int orow = b * N_ + q0 + w * 16 + g;
    #pragma unroll
    for (int df = 0; df < 8; df++) {
        int col = h * 64 + df * 8 + 2 * tg;
        *(__nv_bfloat162*)(attn + (size_t)orow * 512 + col) =
            __floats2bfloat162_rn(Oa[df][0] * inv0, Oa[df][1] * inv0);
        *(__nv_bfloat162*)(attn + (size_t)(orow + 8) * 512 + col) =
            __floats2bfloat162_rn(Oa[df][2] * inv1, Oa[df][3] * inv1);
    }
}

// ---------------- att_topk + prune (round-6 proven) ----------------
__device__ __forceinline__ float blkmax(float v, float* red, int tid) {
    #pragma unroll
    for (int o = 16; o > 0; o >>= 1) v = fmaxf(v, __shfl_xor_sync(0xffffffffu, v, o));
    if ((tid & 31) == 0) red[tid >> 5] = v;
    __syncthreads();
    if (tid < 32) {
        float t = red[tid];
        #pragma unroll
        for (int o = 16; o > 0; o >>= 1) t = fmaxf(t, __shfl_xor_sync(0xffffffffu, t, o));
        if (tid == 0) red[0] = t;
    }
    __syncthreads();
    float r = red[0];
    __syncthreads();
    return r;
}
__device__ __forceinline__ float blksum(float v, float* red, int tid) {
    #pragma unroll
    for (int o = 16; o > 0; o >>= 1) v += __shfl_xor_sync(0xffffffffu, v, o);
    if ((tid & 31) == 0) red[tid >> 5] = v;
    __syncthreads();
    if (tid < 32) {
        float t = red[tid];
        #pragma unroll
        for (int o = 16; o > 0; o >>= 1) t += __shfl_xor_sync(0xffffffffu, t, o);
        if (tid == 0) red[0] = t;
    }
    __syncthreads();
    float r = red[0];
    __syncthreads();
    return r;
}
__global__ void __launch_bounds__(1024) topk0_kernel(const bf16* __restrict__ qkv,
                                                     const float* __restrict__ mask,
                                                     float* __restrict__ topk) {
    int b = blockIdx.x, m = threadIdx.x;
    __shared__ float q0s[512];
    __shared__ float red[32];
    size_t rb = (size_t)b * N_ * 1536;
    if (m < 512) q0s[m] = __bfloat162float(qkv[rb + m]);
    __syncthreads();
    const bf16* krow = qkv + rb + (size_t)m * 1536 + 512;
    float s[8];
    #pragma unroll
    for (int h = 0; h < 8; h++) {
        float acc = 0.0f;
        #pragma unroll
        for (int j = 0; j < 64; j += 8) {
            uint4 kv = *(const uint4*)(krow + h * 64 + j);
            bf16 t[8]; *(uint4*)t = kv;
            #pragma unroll
            for (int i = 0; i < 8; i++) acc += q0s[h * 64 + j + i] * __bfloat162float(t[i]);
        }
        s[h] = acc * 0.125f;
    }
    if (mask[(size_t)b * N_ * N_ + m] == 1.0f)
        #pragma unroll
        for (int h = 0; h < 8; h++) s[h] = NEGBIG;
    float out = 0.0f;
    #pragma unroll
    for (int h = 0; h < 8; h++) {
        float M = blkmax(s[h], red, m);
        float p = __expf(s[h] - M);
        float L = blksum(p, red, m);
        out += p / L;
    }
    topk[b * N_ + m] = out * 0.125f;
}

__global__ void __launch_bounds__(1024) prune_kernel(const float* __restrict__ topk,
                                                     float* __restrict__ out) {
    int b = blockIdx.x, m = threadIdx.x;
    __shared__ float key[N_];
    float km = (m == 0) ? NINF : topk[b * N_ + m];
    key[m] = km;
    __syncthreads();
    int rank = 0;
    for (int j = 0; j < N_; j++) {
        float kj = key[j];
        rank += (kj > km) || (kj == km && j < m);
    }
    if (rank >= 959 && rank < 1023) out[4194304 + b * 64 + (rank - 959)] = (float)m;
    if (m == 0) out[4194816 + b] = -1.0f;
    if (m < 16) out[4194824 + b * 16 + m] = 0.0f;
}

// ------- 16-bit GEMM, cp.async 2-stage, tile 128x128 (round-6 champion) -------
// EPI: 0 = store 16-bit; 2 = +bias+resid -> fp32; 3 = gelu(.+bias) -> 16-bit
template<int EPI, bool HALF>
__global__ void __launch_bounds__(256) gemm_k(
    const uint16_t* __restrict__ A, const uint16_t* __restrict__ Bm, void* __restrict__ Cp,
    int K, int lda, int ldb, int ldc,
    const float* __restrict__ bias, const float* __restrict__ resid)
{
    constexpr int LA = 40, LB = 136;
    __shared__ uint16_t As[2][128 * LA];
    __shared__ uint16_t Bs[2][32 * LB];
    int tid = threadIdx.x, warp = tid >> 5, lane = tid & 31;
    int g = lane >> 2, tg = lane & 3;
    int warpM = warp & 3, warpN = warp >> 2;
    int row0 = blockIdx.y * 128, col0 = blockIdx.x * 128;
    uint32_t sA = (uint32_t)__cvta_generic_to_shared(As);
    uint32_t sB = (uint32_t)__cvta_generic_to_shared(Bs);
    int koff = ((lane >> 3) & 1) * 8 + (lane & 7);
    int nsel = (lane >> 4) * 8;

    float acc[2][8][4];
    #pragma unroll
    for (int a = 0; a < 2; a++)
        #pragma unroll
        for (int b2 = 0; b2 < 8; b2++)
            #pragma unroll
            for (int c = 0; c < 4; c++) acc[a][b2][c] = 0.0f;

    auto issue = [&](int st, int k0) {
        #pragma unroll
        for (int it = 0, c = tid; it < 2; it++, c += 256) {
            int r = c >> 2, kc = (c & 3) * 8;
            cp16(sA + (st * 128 * LA + r * LA + kc) * 2,
                 A + (size_t)(row0 + r) * lda + k0 + kc);
        }
        #pragma unroll
        for (int it = 0, c = tid; it < 2; it++, c += 256) {
            int kk = c >> 4, nc = (c & 15) * 8;
            cp16(sB + (st * 32 * LB + kk * LB + nc) * 2,
                 Bm + (size_t)(k0 + kk) * ldb + col0 + nc);
        }
        cpcommit();
    };

    issue(0, 0);
    int nk = K / 32;
    for (int i = 0; i < nk; i++) {
        int st = i & 1;
        cpwait0();
        __syncthreads();
        if (i + 1 < nk) issue(st ^ 1, (i + 1) * 32);
        const uint16_t* Ab = As[st];
        uint32_t sBst = sB + st * 32 * LB * 2;
        #pragma unroll
        for (int kk = 0; kk < 32; kk += 16) {
            uint32_t af[2][4];
            #pragma unroll
            for (int mt = 0; mt < 2; mt++) {
                const uint16_t* p = &Ab[(warpM * 32 + mt * 16 + g) * LA + kk + 2 * tg];
                af[mt][0] = *(const uint32_t*)p;
                af[mt][1] = *(const uint32_t*)(p + 8 * LA);
                af[mt][2] = *(const uint32_t*)(p + 8);
                af[mt][3] = *(const uint32_t*)(p + 8 * LA + 8);
            }
            #pragma unroll
            for (int p2 = 0; p2 < 4; p2++) {
                uint32_t bq[4];
                ldsm4t(bq, sBst + (uint32_t)((kk + koff) * LB + warpN * 64 + p2 * 16 + nsel) * 2);
                #pragma unroll
                for (int mt = 0; mt < 2; mt++) {
                    mma16816<HALF>(acc[mt][2 * p2], af[mt], bq[0], bq[1]);
                    mma16816<HALF>(acc[mt][2 * p2 + 1], af[mt], bq[2], bq[3]);
                }
            }
        }
        __syncthreads();
    }
    #pragma unroll
    for (int mt = 0; mt < 2; mt++)
        #pragma unroll
        for (int nt = 0; nt < 8; nt++) {
            int r = row0 + warpM * 32 + mt * 16 + g;
            int cc = col0 + warpN * 64 + nt * 8 + 2 * tg;
            #pragma unroll
            for (int hf = 0; hf < 2; hf++) {
                int rr = r + hf * 8;
                float v0 = acc[mt][nt][hf * 2], v1 = acc[mt][nt][hf * 2 + 1];
                long idx = (long)rr * ldc + cc;
                if (EPI == 2) {
                    v0 += bias[cc] + resid[idx];
                    v1 += bias[cc + 1] + resid[idx + 1];
                    *(float2*)((float*)Cp + idx) = make_float2(v0, v1);
                } else {
                    if (EPI == 3) {
                        v0 += bias[cc]; v1 += bias[cc + 1];
                        v0 = 0.5f * v0 * (1.0f + erff(v0 * 0.70710678f));
                        v1 = 0.5f * v1 * (1.0f + erff(v1 * 0.70710678f));
                    }
                    uint32_t pk;
                    if (HALF) { __half2 t = __floats2half2_rn(v0, v1); pk = *(uint32_t*)&t; }
                    else pk = packbf(v0, v1);
                    *(uint32_t*)((uint16_t*)Cp + idx) = pk;
                }
            }
        }
}

// ---------------- host ----------------
template <typename T>
static T* symaddr(const T& sym) {
    void* p = nullptr;
    cudaGetSymbolAddress(&p, sym);
    return (T*)p;
}

extern "C" void kernel_launch(void* const* d_in, const int* in_sizes, int n_in,
                              void* d_out, int out_size) {
    const float* x    = (const float*)d_in[0];
    const float* mask = (const float*)d_in[1];
    const float* Wqkv = (const float*)d_in[2];
    const float* Wout = (const float*)d_in[3];
    const float* bout = (const float*)d_in[4];
    const float* ln1g = (const float*)d_in[5];
    const float* ln1b = (const float*)d_in[6];
    const float* ln2g = (const float*)d_in[7];
    const float* ln2b = (const float*)d_in[8];
    const float* W1   = (const float*)d_in[9];
    const float* b1   = (const float*)d_in[10];
    const float* W2   = (const float*)d_in[11];
    const float* b2   = (const float*)d_in[12];

    bf16* h = (bf16*)symaddr(g_h);
    bf16* qkv = (bf16*)symaddr(g_qkv);
    bf16* attn = (bf16*)symaddr(g_attn);
    float* x1 = (float*)symaddr(g_x1);
    __half* h2h = (__half*)symaddr(g_h2h);
    __half* ffh = (__half*)symaddr(g_ffh);
    float* tk = (float*)symaddr(g_topk);
    uint32_t* mb = (uint32_t*)symaddr(g_mbits);
    bf16* wqkv = (bf16*)symaddr(g_Wqkv);
    bf16* wout = (bf16*)symaddr(g_Wout);
    __half* w1h = (__half*)symaddr(g_W1h);
    __half* w2h = (__half*)symaddr(g_W2h);

    cudaFuncSetAttribute(flash_kernel, cudaFuncAttributeMaxDynamicSharedMemorySize, FL_SMEM);

    cvtall_kernel<<<(NW1 + NW2 + NW3 + NW4 + 255) / 256, 256>>>(
        Wqkv, Wout, W1, W2, wqkv, wout, w1h, w2h);
    maskbits_kernel<<<B_ * N_ * N_ / 256, 256>>>(mask, mb);
    ln_kernel<0><<<ROWS_ / 8, 256>>>(x, ln1g, ln1b, h);

    // qkv = h @ Wqkv  (bf16)
    gemm_k<0, false><<<dim3(12, 64), 256>>>(
        (const uint16_t*)h, (const uint16_t*)wqkv, qkv, D_, D_, 3 * D_, 3 * D_,
        nullptr, nullptr);
    flash_kernel<<<dim3(8, 64), 256, FL_SMEM>>>(qkv, mb, attn);
    topk0_kernel<<<B_, 1024>>>(qkv, mask, tk);
    prune_kernel<<<B_, 1024>>>(tk, (float*)d_out);
    // x1 = x + attn @ Wout + bout  (bf16)
    gemm_k<2, false><<<dim3(4, 64), 256>>>(
        (const uint16_t*)attn, (const uint16_t*)wout, x1, D_, D_, D_, D_,
        bout, x);
    ln_kernel<1><<<ROWS_ / 8, 256>>>(x1, ln2g, ln2b, h2h);
    // ff = gelu(h2 @ W1 + b1)  (fp16)
    gemm_k<3, true><<<dim3(16, 64), 256>>>(
        (const uint16_t*)h2h, (const uint16_t*)w1h, ffh, D_, D_, MLP_, MLP_,
        b1, nullptr);
    // out = x1 + ff @ W2 + b2  (fp16)
    gemm_k<2, true><<<dim3(4, 64), 256>>>(
        (const uint16_t*)ffh, (const uint16_t*)w2h, (float*)d_out, MLP_, MLP_, D_, D_,
        b2, x1);
}

// round 13
// speedup vs baseline: 1.1854x; 1.0257x over previous
#include <cuda_runtime.h>
#include <cuda_bf16.h>
#include <cuda_fp16.h>
#include <cstdint>

using bf16 = __nv_bfloat16;

#define B_ 8
#define N_ 1024
#define D_ 512
#define MLP_ 2048
#define ROWS_ (B_ * N_)
#define NEGBIG (-1e10f)
#define NINF __int_as_float(0xff800000)

// ---------------- scratch ----------------
__device__ bf16  g_h[ROWS_ * D_];
__device__ bf16  g_qkv[ROWS_ * 3 * D_];
__device__ bf16  g_attn[ROWS_ * D_];
__device__ float g_x1[ROWS_ * D_];
__device__ __half g_h2h[ROWS_ * D_];
__device__ __half g_ffh[ROWS_ * MLP_];
__device__ float g_topk[B_ * N_];
__device__ uint32_t g_mbits[B_ * N_ * 32];
__device__ bf16  g_Wqkv[D_ * 3 * D_];
__device__ bf16  g_Wout[D_ * D_];
__device__ __half g_W1h[D_ * MLP_];
__device__ __half g_W2h[MLP_ * D_];

// ---------------- helpers ----------------
template<bool HALF>
__device__ __forceinline__ void mma16816(float* c, const uint32_t* a, uint32_t b0, uint32_t b1) {
    if (HALF)
        asm volatile("mma.sync.aligned.m16n8k16.row.col.f32.f16.f16.f32 "
                     "{%0,%1,%2,%3},{%4,%5,%6,%7},{%8,%9},{%0,%1,%2,%3};\n"
                     : "+f"(c[0]), "+f"(c[1]), "+f"(c[2]), "+f"(c[3])
                     : "r"(a[0]), "r"(a[1]), "r"(a[2]), "r"(a[3]), "r"(b0), "r"(b1));
    else
        asm volatile("mma.sync.aligned.m16n8k16.row.col.f32.bf16.bf16.f32 "
                     "{%0,%1,%2,%3},{%4,%5,%6,%7},{%8,%9},{%0,%1,%2,%3};\n"
                     : "+f"(c[0]), "+f"(c[1]), "+f"(c[2]), "+f"(c[3])
                     : "r"(a[0]), "r"(a[1]), "r"(a[2]), "r"(a[3]), "r"(b0), "r"(b1));
}
__device__ __forceinline__ void ldsm4(uint32_t* r, uint32_t a) {
    asm volatile("ldmatrix.sync.aligned.m8n8.x4.shared.b16 {%0,%1,%2,%3},[%4];"
                 : "=r"(r[0]), "=r"(r[1]), "=r"(r[2]), "=r"(r[3]) : "r"(a));
}
__device__ __forceinline__ void ldsm4t(uint32_t* r, uint32_t a) {
    asm volatile("ldmatrix.sync.aligned.m8n8.x4.trans.shared.b16 {%0,%1,%2,%3},[%4];"
                 : "=r"(r[0]), "=r"(r[1]), "=r"(r[2]), "=r"(r[3]) : "r"(a));
}
__device__ __forceinline__ uint32_t packbf(float x, float y) {
    __nv_bfloat162 t = __floats2bfloat162_rn(x, y);
    return *(uint32_t*)&t;
}
__device__ __forceinline__ void cp16(uint32_t s, const void* g) {
    asm volatile("cp.async.cg.shared.global [%0],[%1],16;\n" :: "r"(s), "l"(g));
}
__device__ __forceinline__ void cp4(uint32_t s, const void* g) {
    asm volatile("cp.async.ca.shared.global [%0],[%1],4;\n" :: "r"(s), "l"(g));
}
__device__ __forceinline__ void cpcommit() { asm volatile("cp.async.commit_group;\n"); }
__device__ __forceinline__ void cpwait0() { asm volatile("cp.async.wait_group 0;\n"); }
__device__ __forceinline__ void cpwait1() { asm volatile("cp.async.wait_group 1;\n"); }

// ---------------- fused weight convert ----------------
#define NW1 786432
#define NW2 262144
#define NW3 1048576
#define NW4 1048576
__global__ void cvtall_kernel(const float* __restrict__ wqkv, const float* __restrict__ wout,
                              const float* __restrict__ w1, const float* __restrict__ w2,
                              bf16* __restrict__ dqkv, bf16* __restrict__ dout,
                              __half* __restrict__ d1, __half* __restrict__ d2) {
    int i = blockIdx.x * blockDim.x + threadIdx.x;
    if (i < NW1) { dqkv[i] = __float2bfloat16(wqkv[i]); return; }
    i -= NW1;
    if (i < NW2) { dout[i] = __float2bfloat16(wout[i]); return; }
    i -= NW2;
    if (i < NW3) { d1[i] = __float2half_rn(w1[i]); return; }
    i -= NW3;
    if (i < NW4) { d2[i] = __float2half_rn(w2[i]); }
}

__global__ void maskbits_kernel(const float* __restrict__ mask, uint32_t* __restrict__ bits) {
    int idx = blockIdx.x * blockDim.x + threadIdx.x;
    uint32_t bal = __ballot_sync(0xffffffffu, mask[idx] == 1.0f);
    if ((idx & 31) == 0) bits[idx >> 5] = bal;
}

// ---------------- LayerNorm: warp-per-row, 8 rows/CTA. OUT: 0=bf16, 1=fp16 ------
template<int OUT>
__global__ void __launch_bounds__(256) ln_kernel(const float* __restrict__ x,
                                                 const float* __restrict__ gam,
                                                 const float* __restrict__ bet,
                                                 void* __restrict__ out) {
    int w = threadIdx.x >> 5, lane = threadIdx.x & 31;
    size_t row = (size_t)blockIdx.x * 8 + w;
    const float4* xr = (const float4*)(x + row * D_);
    float4 v[4];
    float s = 0.0f, sq = 0.0f;
    #pragma unroll
    for (int i = 0; i < 4; i++) {
        v[i] = xr[lane + i * 32];
        s  += v[i].x + v[i].y + v[i].z + v[i].w;
        sq += v[i].x * v[i].x + v[i].y * v[i].y + v[i].z * v[i].z + v[i].w * v[i].w;
    }
    #pragma unroll
    for (int o = 16; o > 0; o >>= 1) {
        s  += __shfl_xor_sync(0xffffffffu, s, o);
        sq += __shfl_xor_sync(0xffffffffu, sq, o);
    }
    float mu = s * (1.0f / D_);
    float rs = rsqrtf(sq * (1.0f / D_) - mu * mu + 1e-5f);
    #pragma unroll
    for (int i = 0; i < 4; i++) {
        int fi = lane + i * 32;
        float4 gv = ((const float4*)gam)[fi];
        float4 bv = ((const float4*)bet)[fi];
        float o0 = (v[i].x - mu) * rs * gv.x + bv.x;
        float o1 = (v[i].y - mu) * rs * gv.y + bv.y;
        float o2 = (v[i].z - mu) * rs * gv.z + bv.z;
        float o3 = (v[i].w - mu) * rs * gv.w + bv.w;
        if (OUT == 0) {
            bf16* o = (bf16*)out + row * D_ + fi * 4;
            ((__nv_bfloat162*)o)[0] = __floats2bfloat162_rn(o0, o1);
            ((__nv_bfloat162*)o)[1] = __floats2bfloat162_rn(o2, o3);
        } else {
            __half* o = (__half*)out + row * D_ + fi * 4;
            ((__half2*)o)[0] = __floats2half2_rn(o0, o1);
            ((__half2*)o)[1] = __floats2half2_rn(o2, o3);
        }
    }
}

// ---------------- flash attention (R6 structure; force 2 CTAs/SM) ----------------
#define LQ 72
#define FL_SMEM (3 * 128 * LQ * 2 + 2 * 512 * 4)
__global__ void __launch_bounds__(256, 2) flash_kernel(const bf16* __restrict__ qkv,
                                                       const uint32_t* __restrict__ mbits,
                                                       bf16* __restrict__ attn) {
    extern __shared__ char sm[];
    uint32_t sQ = (uint32_t)__cvta_generic_to_shared(sm);
    uint32_t sK = sQ + 128 * LQ * 2;
    uint32_t sV = sK + 128 * LQ * 2;
    uint32_t sM = sV + 128 * LQ * 2;
    uint32_t* mw = (uint32_t*)(sm + 3 * 128 * LQ * 2);

    int bh = blockIdx.y, b = bh >> 3, h = bh & 7;
    int tid = threadIdx.x, w = tid >> 5, lane = tid & 31, g = lane >> 2, tg = lane & 3;
    int q0 = blockIdx.x * 128;
    size_t base = (size_t)b * N_ * 1536;

    #pragma unroll
    for (int it = 0, c = tid; it < 4; it++, c += 256) {
        int r = c >> 3, d0 = (c & 7) * 8;
        cp16(sQ + (r * LQ + d0) * 2, qkv + base + (size_t)(q0 + r) * 1536 + h * 64 + d0);
        cp16(sK + (r * LQ + d0) * 2, qkv + base + (size_t)r * 1536 + 512 + h * 64 + d0);
    }
    #pragma unroll
    for (int it = 0, c = tid; it < 2; it++, c += 256)
        cp4(sM + c * 4, &mbits[((size_t)b * N_ + q0 + (c >> 2)) * 32 + (c & 3)]);
    cpcommit();

    float Oa[8][4];
    #pragma unroll
    for (int i = 0; i < 8; i++)
        #pragma unroll
        for (int j = 0; j < 4; j++) Oa[i][j] = 0.0f;
    float mrow0 = NINF, mrow1 = NINF, lrow0 = 0.0f, lrow1 = 0.0f;

    int aRow = w * 16 + ((lane >> 3) & 1) * 8 + (lane & 7);
    int aSel = (lane >> 4) * 8;
    int bRowOff = (lane >> 4) * 8 + (lane & 7);
    int bSel = ((lane >> 3) & 1) * 8;
    int vKeyOff = ((lane >> 3) & 1) * 8 + (lane & 7);
    int vDSel = (lane >> 4);

    cpwait0();
    __syncthreads();

    for (int kt = 0; kt < 8; kt++) {
        int cur = kt & 1;
        #pragma unroll
        for (int it = 0, c = tid; it < 4; it++, c += 256) {
            int r = c >> 3, d0 = (c & 7) * 8;
            cp16(sV + (r * LQ + d0) * 2,
                 qkv + base + (size_t)(kt * 128 + r) * 1536 + 1024 + h * 64 + d0);
        }
        cpcommit();

        float sacc[16][4];
        #pragma unroll
        for (int nf = 0; nf < 16; nf++)
            #pragma unroll
            for (int j = 0; j < 4; j++) sacc[nf][j] = 0.0f;
        #pragma unroll
        for (int kk = 0; kk < 64; kk += 16) {
            uint32_t aq[4];
            ldsm4(aq, sQ + (uint32_t)(aRow * LQ + kk + aSel) * 2);
            #pragma unroll
            for (int nfp = 0; nfp < 8; nfp++) {
                uint32_t bq[4];
                ldsm4(bq, sK + (uint32_t)((nfp * 16 + bRowOff) * LQ + kk + bSel) * 2);
                mma16816<false>(sacc[2 * nfp], aq, bq[0], bq[1]);
                mma16816<false>(sacc[2 * nfp + 1], aq, bq[2], bq[3]);
            }
        }

        int r0l = w * 16 + g;
        uint32_t mwa[4], mwb[4];
        #pragma unroll
        for (int i = 0; i < 4; i++) {
            mwa[i] = mw[cur * 512 + r0l * 4 + i];
            mwb[i] = mw[cur * 512 + (r0l + 8) * 4 + i];
        }
        float mx0 = -3e38f, mx1 = -3e38f;
        #pragma unroll
        for (int nf = 0; nf < 16; nf++) {
            int c0 = nf * 8 + 2 * tg;
            uint32_t wa = mwa[c0 >> 5], wb = mwb[c0 >> 5];
            int shm = c0 & 31;
            float s00 = ((wa >> shm) & 1) ? NEGBIG : sacc[nf][0] * 0.125f;
            float s01 = ((wa >> (shm + 1)) & 1) ? NEGBIG : sacc[nf][1] * 0.125f;
            float s10 = ((wb >> shm) & 1) ? NEGBIG : sacc[nf][2] * 0.125f;
            float s11 = ((wb >> (shm + 1)) & 1) ? NEGBIG : sacc[nf][3] * 0.125f;
            sacc[nf][0] = s00; sacc[nf][1] = s01; sacc[nf][2] = s10; sacc[nf][3] = s11;
            mx0 = fmaxf(mx0, fmaxf(s00, s01));
            mx1 = fmaxf(mx1, fmaxf(s10, s11));
        }
        mx0 = fmaxf(mx0, __shfl_xor_sync(0xffffffffu, mx0, 1));
        mx0 = fmaxf(mx0, __shfl_xor_sync(0xffffffffu, mx0, 2));
        mx1 = fmaxf(mx1, __shfl_xor_sync(0xffffffffu, mx1, 1));
        mx1 = fmaxf(mx1, __shfl_xor_sync(0xffffffffu, mx1, 2));
        float mn0 = fmaxf(mrow0, mx0), mn1 = fmaxf(mrow1, mx1);
        float cf0 = __expf(mrow0 - mn0), cf1 = __expf(mrow1 - mn1);
        mrow0 = mn0; mrow1 = mn1;
        float rs0 = 0.0f, rs1 = 0.0f;
        #pragma unroll
        for (int nf = 0; nf < 16; nf++) {
            float p00 = __expf(sacc[nf][0] - mn0);
            float p01 = __expf(sacc[nf][1] - mn0);
            float p10 = __expf(sacc[nf][2] - mn1);
            float p11 = __expf(sacc[nf][3] - mn1);
            sacc[nf][0] = p00; sacc[nf][1] = p01; sacc[nf][2] = p10; sacc[nf][3] = p11;
            rs0 += p00 + p01; rs1 += p10 + p11;
        }
        rs0 += __shfl_xor_sync(0xffffffffu, rs0, 1);
        rs0 += __shfl_xor_sync(0xffffffffu, rs0, 2);
        rs1 += __shfl_xor_sync(0xffffffffu, rs1, 1);
        rs1 += __shfl_xor_sync(0xffffffffu, rs1, 2);
        lrow0 = lrow0 * cf0 + rs0;
        lrow1 = lrow1 * cf1 + rs1;
        #pragma unroll
        for (int df = 0; df < 8; df++) {
            Oa[df][0] *= cf0; Oa[df][1] *= cf0;
            Oa[df][2] *= cf1; Oa[df][3] *= cf1;
        }
        uint32_t pa[8][4];
        #pragma unroll
        for (int f = 0; f < 8; f++) {
            pa[f][0] = packbf(sacc[2 * f][0], sacc[2 * f][1]);
            pa[f][1] = packbf(sacc[2 * f][2], sacc[2 * f][3]);
            pa[f][2] = packbf(sacc[2 * f + 1][0], sacc[2 * f + 1][1]);
            pa[f][3] = packbf(sacc[2 * f + 1][2], sacc[2 * f + 1][3]);
        }
        __syncthreads();

        bool more = kt < 7;
        if (more) {
            #pragma unroll
            for (int it = 0, c = tid; it < 4; it++, c += 256) {
                int r = c >> 3, d0 = (c & 7) * 8;
                cp16(sK + (r * LQ + d0) * 2,
                     qkv + base + (size_t)((kt + 1) * 128 + r) * 1536 + 512 + h * 64 + d0);
            }
            #pragma unroll
            for (int it = 0, c = tid; it < 2; it++, c += 256)
                cp4(sM + ((cur ^ 1) * 512 + c) * 4,
                    &mbits[((size_t)b * N_ + q0 + (c >> 2)) * 32 + (kt + 1) * 4 + (c & 3)]);
            cpcommit();
            cpwait1();
        } else {
            cpwait0();
        }
        __syncthreads();

        #pragma unroll
        for (int f = 0; f < 8; f++) {
            #pragma unroll
            for (int q = 0; q < 4; q++) {
                uint32_t bv[4];
                ldsm4t(bv, sV + (uint32_t)((f * 16 + vKeyOff) * LQ + (vDSel + 2 * q) * 8) * 2);
                mma16816<false>(Oa[2 * q], pa[f], bv[0], bv[1]);
                mma16816<false>(Oa[2 * q + 1], pa[f], bv[2], bv[3]);
            }
        }
        cpwait0();
        __syncthreads();
    }

    float inv0 = 1.0f / lrow0, inv1 = 1.0f / lrow1;
    int orow = b * N_ + q0 + w * 16 + g;
    #pragma unroll
    for (int df = 0; df < 8; df++) {
        int col = h * 64 + df * 8 + 2 * tg;
        *(__nv_bfloat162*)(attn + (size_t)orow * 512 + col) =
            __floats2bfloat162_rn(Oa[df][0] * inv0, Oa[df][1] * inv0);
        *(__nv_bfloat162*)(attn + (size_t)(orow + 8) * 512 + col) =
            __floats2bfloat162_rn(Oa[df][2] * inv1, Oa[df][3] * inv1);
    }
}

// ---------------- att_topk + prune (round-6 proven) ----------------
__device__ __forceinline__ float blkmax(float v, float* red, int tid) {
    #pragma unroll
    for (int o = 16; o > 0; o >>= 1) v = fmaxf(v, __shfl_xor_sync(0xffffffffu, v, o));
    if ((tid & 31) == 0) red[tid >> 5] = v;
    __syncthreads();
    if (tid < 32) {
        float t = red[tid];
        #pragma unroll
        for (int o = 16; o > 0; o >>= 1) t = fmaxf(t, __shfl_xor_sync(0xffffffffu, t, o));
        if (tid == 0) red[0] = t;
    }
    __syncthreads();
    float r = red[0];
    __syncthreads();
    return r;
}
__device__ __forceinline__ float blksum(float v, float* red, int tid) {
    #pragma unroll
    for (int o = 16; o > 0; o >>= 1) v += __shfl_xor_sync(0xffffffffu, v, o);
    if ((tid & 31) == 0) red[tid >> 5] = v;
    __syncthreads();
    if (tid < 32) {
        float t = red[tid];
        #pragma unroll
        for (int o = 16; o > 0; o >>= 1) t += __shfl_xor_sync(0xffffffffu, t, o);
        if (tid == 0) red[0] = t;
    }
    __syncthreads();
    float r = red[0];
    __syncthreads();
    return r;
}
__global__ void __launch_bounds__(1024) topk0_kernel(const bf16* __restrict__ qkv,
                                                     const float* __restrict__ mask,
                                                     float* __restrict__ topk) {
    int b = blockIdx.x, m = threadIdx.x;
    __shared__ float q0s[512];
    __shared__ float red[32];
    size_t rb = (size_t)b * N_ * 1536;
    if (m < 512) q0s[m] = __bfloat162float(qkv[rb + m]);
    __syncthreads();
    const bf16* krow = qkv + rb + (size_t)m * 1536 + 512;
    float s[8];
    #pragma unroll
    for (int h = 0; h < 8; h++) {
        float acc = 0.0f;
        #pragma unroll
        for (int j = 0; j < 64; j += 8) {
            uint4 kv = *(const uint4*)(krow + h * 64 + j);
            bf16 t[8]; *(uint4*)t = kv;
            #pragma unroll
            for (int i = 0; i < 8; i++) acc += q0s[h * 64 + j + i] * __bfloat162float(t[i]);
        }
        s[h] = acc * 0.125f;
    }
    if (mask[(size_t)b * N_ * N_ + m] == 1.0f)
        #pragma unroll
        for (int h = 0; h < 8; h++) s[h] = NEGBIG;
    float out = 0.0f;
    #pragma unroll
    for (int h = 0; h < 8; h++) {
        float M = blkmax(s[h], red, m);
        float p = __expf(s[h] - M);
        float L = blksum(p, red, m);
        out += p / L;
    }
    topk[b * N_ + m] = out * 0.125f;
}

__global__ void __launch_bounds__(1024) prune_kernel(const float* __restrict__ topk,
                                                     float* __restrict__ out) {
    int b = blockIdx.x, m = threadIdx.x;
    __shared__ float key[N_];
    float km = (m == 0) ? NINF : topk[b * N_ + m];
    key[m] = km;
    __syncthreads();
    int rank = 0;
    for (int j = 0; j < N_; j++) {
        float kj = key[j];
        rank += (kj > km) || (kj == km && j < m);
    }
    if (rank >= 959 && rank < 1023) out[4194304 + b * 64 + (rank - 959)] = (float)m;
    if (m == 0) out[4194816 + b] = -1.0f;
    if (m < 16) out[4194824 + b * 16 + m] = 0.0f;
}

// ------- 16-bit GEMM, cp.async 2-stage, tile 128x128 (round-6 champion) -------
// EPI: 0 = store 16-bit; 2 = +bias+resid -> fp32; 3 = gelu(.+bias) -> 16-bit
template<int EPI, bool HALF>
__global__ void __launch_bounds__(256) gemm_k(
    const uint16_t* __restrict__ A, const uint16_t* __restrict__ Bm, void* __restrict__ Cp,
    int K, int lda, int ldb, int ldc,
    const float* __restrict__ bias, const float* __restrict__ resid)
{
    constexpr int LA = 40, LB = 136;
    __shared__ uint16_t As[2][128 * LA];
    __shared__ uint16_t Bs[2][32 * LB];
    int tid = threadIdx.x, warp = tid >> 5, lane = tid & 31;
    int g = lane >> 2, tg = lane & 3;
    int warpM = warp & 3, warpN = warp >> 2;
    int row0 = blockIdx.y * 128, col0 = blockIdx.x * 128;
    uint32_t sA = (uint32_t)__cvta_generic_to_shared(As);
    uint32_t sB = (uint32_t)__cvta_generic_to_shared(Bs);
    int koff = ((lane >> 3) & 1) * 8 + (lane & 7);
    int nsel = (lane >> 4) * 8;

    float acc[2][8][4];
    #pragma unroll
    for (int a = 0; a < 2; a++)
        #pragma unroll
        for (int b2 = 0; b2 < 8; b2++)
            #pragma unroll
            for (int c = 0; c < 4; c++) acc[a][b2][c] = 0.0f;

    auto issue = [&](int st, int k0) {
        #pragma unroll
        for (int it = 0, c = tid; it < 2; it++, c += 256) {
            int r = c >> 2, kc = (c & 3) * 8;
            cp16(sA + (st * 128 * LA + r * LA + kc) * 2,
                 A + (size_t)(row0 + r) * lda + k0 + kc);
        }
        #pragma unroll
        for (int it = 0, c = tid; it < 2; it++, c += 256) {
            int kk = c >> 4, nc = (c & 15) * 8;
            cp16(sB + (st * 32 * LB + kk * LB + nc) * 2,
                 Bm + (size_t)(k0 + kk) * ldb + col0 + nc);
        }
        cpcommit();
    };

    issue(0, 0);
    int nk = K / 32;
    for (int i = 0; i < nk; i++) {
        int st = i & 1;
        cpwait0();
        __syncthreads();
        if (i + 1 < nk) issue(st ^ 1, (i + 1) * 32);
        const uint16_t* Ab = As[st];
        uint32_t sBst = sB + st * 32 * LB * 2;
        #pragma unroll
        for (int kk = 0; kk < 32; kk += 16) {
            uint32_t af[2][4];
            #pragma unroll
            for (int mt = 0; mt < 2; mt++) {
                const uint16_t* p = &Ab[(warpM * 32 + mt * 16 + g) * LA + kk + 2 * tg];
                af[mt][0] = *(const uint32_t*)p;
                af[mt][1] = *(const uint32_t*)(p + 8 * LA);
                af[mt][2] = *(const uint32_t*)(p + 8);
                af[mt][3] = *(const uint32_t*)(p + 8 * LA + 8);
            }
            #pragma unroll
            for (int p2 = 0; p2 < 4; p2++) {
                uint32_t bq[4];
                ldsm4t(bq, sBst + (uint32_t)((kk + koff) * LB + warpN * 64 + p2 * 16 + nsel) * 2);
                #pragma unroll
                for (int mt = 0; mt < 2; mt++) {
                    mma16816<HALF>(acc[mt][2 * p2], af[mt], bq[0], bq[1]);
                    mma16816<HALF>(acc[mt][2 * p2 + 1], af[mt], bq[2], bq[3]);
                }
            }
        }
        __syncthreads();
    }
    #pragma unroll
    for (int mt = 0; mt < 2; mt++)
        #pragma unroll
        for (int nt = 0; nt < 8; nt++) {
            int r = row0 + warpM * 32 + mt * 16 + g;
            int cc = col0 + warpN * 64 + nt * 8 + 2 * tg;
            #pragma unroll
            for (int hf = 0; hf < 2; hf++) {
                int rr = r + hf * 8;
                float v0 = acc[mt][nt][hf * 2], v1 = acc[mt][nt][hf * 2 + 1];
                long idx = (long)rr * ldc + cc;
                if (EPI == 2) {
                    v0 += bias[cc] + resid[idx];
                    v1 += bias[cc + 1] + resid[idx + 1];
                    *(float2*)((float*)Cp + idx) = make_float2(v0, v1);
                } else {
                    if (EPI == 3) {
                        v0 += bias[cc]; v1 += bias[cc + 1];
                        v0 = 0.5f * v0 * (1.0f + erff(v0 * 0.70710678f));
                        v1 = 0.5f * v1 * (1.0f + erff(v1 * 0.70710678f));
                    }
                    uint32_t pk;
                    if (HALF) { __half2 t = __floats2half2_rn(v0, v1); pk = *(uint32_t*)&t; }
                    else pk = packbf(v0, v1);
                    *(uint32_t*)((uint16_t*)Cp + idx) = pk;
                }
            }
        }
}

// ---------------- host ----------------
template <typename T>
static T* symaddr(const T& sym) {
    void* p = nullptr;
    cudaGetSymbolAddress(&p, sym);
    return (T*)p;
}

extern "C" void kernel_launch(void* const* d_in, const int* in_sizes, int n_in,
                              void* d_out, int out_size) {
    const float* x    = (const float*)d_in[0];
    const float* mask = (const float*)d_in[1];
    const float* Wqkv = (const float*)d_in[2];
    const float* Wout = (const float*)d_in[3];
    const float* bout = (const float*)d_in[4];
    const float* ln1g = (const float*)d_in[5];
    const float* ln1b = (const float*)d_in[6];
    const float* ln2g = (const float*)d_in[7];
    const float* ln2b = (const float*)d_in[8];
    const float* W1   = (const float*)d_in[9];
    const float* b1   = (const float*)d_in[10];
    const float* W2   = (const float*)d_in[11];
    const float* b2   = (const float*)d_in[12];

    bf16* h = (bf16*)symaddr(g_h);
    bf16* qkv = (bf16*)symaddr(g_qkv);
    bf16* attn = (bf16*)symaddr(g_attn);
    float* x1 = (float*)symaddr(g_x1);
    __half* h2h = (__half*)symaddr(g_h2h);
    __half* ffh = (__half*)symaddr(g_ffh);
    float* tk = (float*)symaddr(g_topk);
    uint32_t* mb = (uint32_t*)symaddr(g_mbits);
    bf16* wqkv = (bf16*)symaddr(g_Wqkv);
    bf16* wout = (bf16*)symaddr(g_Wout);
    __half* w1h = (__half*)symaddr(g_W1h);
    __half* w2h = (__half*)symaddr(g_W2h);

    cudaFuncSetAttribute(flash_kernel, cudaFuncAttributeMaxDynamicSharedMemorySize, FL_SMEM);

    cvtall_kernel<<<(NW1 + NW2 + NW3 + NW4 + 255) / 256, 256>>>(
        Wqkv, Wout, W1, W2, wqkv, wout, w1h, w2h);
    maskbits_kernel<<<B_ * N_ * N_ / 256, 256>>>(mask, mb);
    ln_kernel<0><<<ROWS_ / 8, 256>>>(x, ln1g, ln1b, h);

    // qkv = h @ Wqkv  (bf16)
    gemm_k<0, false><<<dim3(12, 64), 256>>>(
        (const uint16_t*)h, (const uint16_t*)wqkv, qkv, D_, D_, 3 * D_, 3 * D_,
        nullptr, nullptr);
    flash_kernel<<<dim3(8, 64), 256, FL_SMEM>>>(qkv, mb, attn);
    topk0_kernel<<<B_, 1024>>>(qkv, mask, tk);
    prune_kernel<<<B_, 1024>>>(tk, (float*)d_out);
    // x1 = x + attn @ Wout + bout  (bf16)
    gemm_k<2, false><<<dim3(4, 64), 256>>>(
        (const uint16_t*)attn, (const uint16_t*)wout, x1, D_, D_, D_, D_,
        bout, x);
    ln_kernel<1><<<ROWS_ / 8, 256>>>(x1, ln2g, ln2b, h2h);
    // ff = gelu(h2 @ W1 + b1)  (fp16)
    gemm_k<3, true><<<dim3(16, 64), 256>>>(
        (const uint16_t*)h2h, (const uint16_t*)w1h, ffh, D_, D_, MLP_, MLP_,
        b1, nullptr);
    // out = x1 + ff @ W2 + b2  (fp16)
    gemm_k<2, true><<<dim3(4, 64), 256>>>(
        (const uint16_t*)ffh, (const uint16_t*)w2h, (float*)d_out, MLP_, MLP_, D_, D_,
        b2, x1);
}

// round 14
// speedup vs baseline: 1.1865x; 1.0010x over previous
#include <cuda_runtime.h>
#include <cuda_bf16.h>
#include <cuda_fp16.h>
#include <cstdint>

using bf16 = __nv_bfloat16;

#define B_ 8
#define N_ 1024
#define D_ 512
#define MLP_ 2048
#define ROWS_ (B_ * N_)
#define NEGBIG (-1e10f)
#define NINF __int_as_float(0xff800000)

// ---------------- scratch ----------------
__device__ bf16  g_h[ROWS_ * D_];
__device__ bf16  g_qkv[ROWS_ * 3 * D_];
__device__ bf16  g_attn[ROWS_ * D_];
__device__ float g_x1[ROWS_ * D_];
__device__ __half g_h2h[ROWS_ * D_];
__device__ __half g_ffh[ROWS_ * MLP_];
__device__ float g_topk[B_ * N_];
__device__ uint32_t g_mbits[B_ * N_ * 32];
__device__ bf16  g_Wqkv[D_ * 3 * D_];
__device__ bf16  g_Wout[D_ * D_];
__device__ __half g_W1h[D_ * MLP_];
__device__ __half g_W2h[MLP_ * D_];

// ---------------- helpers ----------------
template<bool HALF>
__device__ __forceinline__ void mma16816(float* c, const uint32_t* a, uint32_t b0, uint32_t b1) {
    if (HALF)
        asm volatile("mma.sync.aligned.m16n8k16.row.col.f32.f16.f16.f32 "
                     "{%0,%1,%2,%3},{%4,%5,%6,%7},{%8,%9},{%0,%1,%2,%3};\n"
                     : "+f"(c[0]), "+f"(c[1]), "+f"(c[2]), "+f"(c[3])
                     : "r"(a[0]), "r"(a[1]), "r"(a[2]), "r"(a[3]), "r"(b0), "r"(b1));
    else
        asm volatile("mma.sync.aligned.m16n8k16.row.col.f32.bf16.bf16.f32 "
                     "{%0,%1,%2,%3},{%4,%5,%6,%7},{%8,%9},{%0,%1,%2,%3};\n"
                     : "+f"(c[0]), "+f"(c[1]), "+f"(c[2]), "+f"(c[3])
                     : "r"(a[0]), "r"(a[1]), "r"(a[2]), "r"(a[3]), "r"(b0), "r"(b1));
}
__device__ __forceinline__ void ldsm4(uint32_t* r, uint32_t a) {
    asm volatile("ldmatrix.sync.aligned.m8n8.x4.shared.b16 {%0,%1,%2,%3},[%4];"
                 : "=r"(r[0]), "=r"(r[1]), "=r"(r[2]), "=r"(r[3]) : "r"(a));
}
__device__ __forceinline__ void ldsm4t(uint32_t* r, uint32_t a) {
    asm volatile("ldmatrix.sync.aligned.m8n8.x4.trans.shared.b16 {%0,%1,%2,%3},[%4];"
                 : "=r"(r[0]), "=r"(r[1]), "=r"(r[2]), "=r"(r[3]) : "r"(a));
}
__device__ __forceinline__ uint32_t packbf(float x, float y) {
    __nv_bfloat162 t = __floats2bfloat162_rn(x, y);
    return *(uint32_t*)&t;
}
__device__ __forceinline__ void cp16(uint32_t s, const void* g) {
    asm volatile("cp.async.cg.shared.global [%0],[%1],16;\n" :: "r"(s), "l"(g));
}
__device__ __forceinline__ void cp4(uint32_t s, const void* g) {
    asm volatile("cp.async.ca.shared.global [%0],[%1],4;\n" :: "r"(s), "l"(g));
}
__device__ __forceinline__ void cpcommit() { asm volatile("cp.async.commit_group;\n"); }
__device__ __forceinline__ void cpwait0() { asm volatile("cp.async.wait_group 0;\n"); }
__device__ __forceinline__ void cpwait2() { asm volatile("cp.async.wait_group 2;\n"); }

// ---------------- fused weight convert ----------------
#define NW1 786432
#define NW2 262144
#define NW3 1048576
#define NW4 1048576
__global__ void cvtall_kernel(const float* __restrict__ wqkv, const float* __restrict__ wout,
                              const float* __restrict__ w1, const float* __restrict__ w2,
                              bf16* __restrict__ dqkv, bf16* __restrict__ dout,
                              __half* __restrict__ d1, __half* __restrict__ d2) {
    int i = blockIdx.x * blockDim.x + threadIdx.x;
    if (i < NW1) { dqkv[i] = __float2bfloat16(wqkv[i]); return; }
    i -= NW1;
    if (i < NW2) { dout[i] = __float2bfloat16(wout[i]); return; }
    i -= NW2;
    if (i < NW3) { d1[i] = __float2half_rn(w1[i]); return; }
    i -= NW3;
    if (i < NW4) { d2[i] = __float2half_rn(w2[i]); }
}

__global__ void maskbits_kernel(const float* __restrict__ mask, uint32_t* __restrict__ bits) {
    int idx = blockIdx.x * blockDim.x + threadIdx.x;
    uint32_t bal = __ballot_sync(0xffffffffu, mask[idx] == 1.0f);
    if ((idx & 31) == 0) bits[idx >> 5] = bal;
}

// ---------------- LayerNorm: warp-per-row, 8 rows/CTA. OUT: 0=bf16, 1=fp16 ------
template<int OUT>
__global__ void __launch_bounds__(256) ln_kernel(const float* __restrict__ x,
                                                 const float* __restrict__ gam,
                                                 const float* __restrict__ bet,
                                                 void* __restrict__ out) {
    int w = threadIdx.x >> 5, lane = threadIdx.x & 31;
    size_t row = (size_t)blockIdx.x * 8 + w;
    const float4* xr = (const float4*)(x + row * D_);
    float4 v[4];
    float s = 0.0f, sq = 0.0f;
    #pragma unroll
    for (int i = 0; i < 4; i++) {
        v[i] = xr[lane + i * 32];
        s  += v[i].x + v[i].y + v[i].z + v[i].w;
        sq += v[i].x * v[i].x + v[i].y * v[i].y + v[i].z * v[i].z + v[i].w * v[i].w;
    }
    #pragma unroll
    for (int o = 16; o > 0; o >>= 1) {
        s  += __shfl_xor_sync(0xffffffffu, s, o);
        sq += __shfl_xor_sync(0xffffffffu, sq, o);
    }
    float mu = s * (1.0f / D_);
    float rs = rsqrtf(sq * (1.0f / D_) - mu * mu + 1e-5f);
    #pragma unroll
    for (int i = 0; i < 4; i++) {
        int fi = lane + i * 32;
        float4 gv = ((const float4*)gam)[fi];
        float4 bv = ((const float4*)bet)[fi];
        float o0 = (v[i].x - mu) * rs * gv.x + bv.x;
        float o1 = (v[i].y - mu) * rs * gv.y + bv.y;
        float o2 = (v[i].z - mu) * rs * gv.z + bv.z;
        float o3 = (v[i].w - mu) * rs * gv.w + bv.w;
        if (OUT == 0) {
            bf16* o = (bf16*)out + row * D_ + fi * 4;
            ((__nv_bfloat162*)o)[0] = __floats2bfloat162_rn(o0, o1);
            ((__nv_bfloat162*)o)[1] = __floats2bfloat162_rn(o2, o3);
        } else {
            __half* o = (__half*)out + row * D_ + fi * 4;
            ((__half2*)o)[0] = __floats2half2_rn(o0, o1);
            ((__half2*)o)[1] = __floats2half2_rn(o2, o3);
        }
    }
}

// ------- flash attention: 2-deep K/V ring, 2 syncs/iter, full-iter prefetch -----
#define LQ 72
#define FTILE (128 * LQ * 2)                       // 18432
#define FL_SMEM (5 * FTILE + 2 * 512 * 4)          // 96256
__global__ void __launch_bounds__(256, 2) flash_kernel(const bf16* __restrict__ qkv,
                                                       const uint32_t* __restrict__ mbits,
                                                       bf16* __restrict__ attn) {
    extern __shared__ char sm[];
    uint32_t sQ = (uint32_t)__cvta_generic_to_shared(sm);
    uint32_t sKb[2] = {sQ + FTILE, sQ + 2 * FTILE};
    uint32_t sVb[2] = {sQ + 3 * FTILE, sQ + 4 * FTILE};
    uint32_t* mw = (uint32_t*)(sm + 5 * FTILE);

    int bh = blockIdx.y, b = bh >> 3, h = bh & 7;
    int tid = threadIdx.x, w = tid >> 5, lane = tid & 31, g = lane >> 2, tg = lane & 3;
    int q0 = blockIdx.x * 128;
    size_t base = (size_t)b * N_ * 1536;

    auto issueK = [&](int kt) {   // K tile kt + its mask words -> parity buffer
        uint32_t dst = sKb[kt & 1];
        #pragma unroll
        for (int it = 0, c = tid; it < 4; it++, c += 256) {
            int r = c >> 3, d0 = (c & 7) * 8;
            cp16(dst + (r * LQ + d0) * 2,
                 qkv + base + (size_t)(kt * 128 + r) * 1536 + 512 + h * 64 + d0);
        }
        uint32_t sMW = sQ + 5 * FTILE + (uint32_t)((kt & 1) * 512) * 4;
        #pragma unroll
        for (int it = 0, c = tid; it < 2; it++, c += 256)
            cp4(sMW + c * 4, &mbits[((size_t)b * N_ + q0 + (c >> 2)) * 32 + kt * 4 + (c & 3)]);
        cpcommit();
    };
    auto issueV = [&](int kt) {
        uint32_t dst = sVb[kt & 1];
        #pragma unroll
        for (int it = 0, c = tid; it < 4; it++, c += 256) {
            int r = c >> 3, d0 = (c & 7) * 8;
            cp16(dst + (r * LQ + d0) * 2,
                 qkv + base + (size_t)(kt * 128 + r) * 1536 + 1024 + h * 64 + d0);
        }
        cpcommit();
    };

    // prologue: {Q+K0+M0}, {V0}, {K1+M1}, {V1}
    #pragma unroll
    for (int it = 0, c = tid; it < 4; it++, c += 256) {
        int r = c >> 3, d0 = (c & 7) * 8;
        cp16(sQ + (r * LQ + d0) * 2, qkv + base + (size_t)(q0 + r) * 1536 + h * 64 + d0);
    }
    issueK(0);          // commits {Q, K0, M0}
    issueV(0);
    issueK(1);
    issueV(1);

    float Oa[8][4];
    #pragma unroll
    for (int i = 0; i < 8; i++)
        #pragma unroll
        for (int j = 0; j < 4; j++) Oa[i][j] = 0.0f;
    float mrow0 = NINF, mrow1 = NINF, lrow0 = 0.0f, lrow1 = 0.0f;

    int aRow = w * 16 + ((lane >> 3) & 1) * 8 + (lane & 7);
    int aSel = (lane >> 4) * 8;
    int bRowOff = (lane >> 4) * 8 + (lane & 7);
    int bSel = ((lane >> 3) & 1) * 8;
    int vKeyOff = ((lane >> 3) & 1) * 8 + (lane & 7);
    int vDSel = (lane >> 4);

    for (int kt = 0; kt < 8; kt++) {
        int cur = kt & 1;
        if (kt < 7) cpwait2(); else cpwait0();   // K[kt], V[kt] landed
        __syncthreads();

        uint32_t sK = sKb[cur], sV = sVb[cur];
        float sacc[16][4];
        #pragma unroll
        for (int nf = 0; nf < 16; nf++)
            #pragma unroll
            for (int j = 0; j < 4; j++) sacc[nf][j] = 0.0f;
        #pragma unroll
        for (int kk = 0; kk < 64; kk += 16) {
            uint32_t aq[4];
            ldsm4(aq, sQ + (uint32_t)(aRow * LQ + kk + aSel) * 2);
            #pragma unroll
            for (int nfp = 0; nfp < 8; nfp++) {
                uint32_t bq[4];
                ldsm4(bq, sK + (uint32_t)((nfp * 16 + bRowOff) * LQ + kk + bSel) * 2);
                mma16816<false>(sacc[2 * nfp], aq, bq[0], bq[1]);
                mma16816<false>(sacc[2 * nfp + 1], aq, bq[2], bq[3]);
            }
        }

        int r0l = w * 16 + g;
        uint32_t mwa[4], mwb[4];
        #pragma unroll
        for (int i = 0; i < 4; i++) {
            mwa[i] = mw[cur * 512 + r0l * 4 + i];
            mwb[i] = mw[cur * 512 + (r0l + 8) * 4 + i];
        }
        float mx0 = -3e38f, mx1 = -3e38f;
        #pragma unroll
        for (int nf = 0; nf < 16; nf++) {
            int c0 = nf * 8 + 2 * tg;
            uint32_t wa = mwa[c0 >> 5], wb = mwb[c0 >> 5];
            int shm = c0 & 31;
            float s00 = ((wa >> shm) & 1) ? NEGBIG : sacc[nf][0] * 0.125f;
            float s01 = ((wa >> (shm + 1)) & 1) ? NEGBIG : sacc[nf][1] * 0.125f;
            float s10 = ((wb >> shm) & 1) ? NEGBIG : sacc[nf][2] * 0.125f;
            float s11 = ((wb >> (shm + 1)) & 1) ? NEGBIG : sacc[nf][3] * 0.125f;
            sacc[nf][0] = s00; sacc[nf][1] = s01; sacc[nf][2] = s10; sacc[nf][3] = s11;
            mx0 = fmaxf(mx0, fmaxf(s00, s01));
            mx1 = fmaxf(mx1, fmaxf(s10, s11));
        }
        mx0 = fmaxf(mx0, __shfl_xor_sync(0xffffffffu, mx0, 1));
        mx0 = fmaxf(mx0, __shfl_xor_sync(0xffffffffu, mx0, 2));
        mx1 = fmaxf(mx1, __shfl_xor_sync(0xffffffffu, mx1, 1));
        mx1 = fmaxf(mx1, __shfl_xor_sync(0xffffffffu, mx1, 2));
        float mn0 = fmaxf(mrow0, mx0), mn1 = fmaxf(mrow1, mx1);
        float cf0 = __expf(mrow0 - mn0), cf1 = __expf(mrow1 - mn1);
        mrow0 = mn0; mrow1 = mn1;
        float rs0 = 0.0f, rs1 = 0.0f;
        #pragma unroll
        for (int nf = 0; nf < 16; nf++) {
            float p00 = __expf(sacc[nf][0] - mn0);
            float p01 = __expf(sacc[nf][1] - mn0);
            float p10 = __expf(sacc[nf][2] - mn1);
            float p11 = __expf(sacc[nf][3] - mn1);
            sacc[nf][0] = p00; sacc[nf][1] = p01; sacc[nf][2] = p10; sacc[nf][3] = p11;
            rs0 += p00 + p01; rs1 += p10 + p11;
        }
        rs0 += __shfl_xor_sync(0xffffffffu, rs0, 1);
        rs0 += __shfl_xor_sync(0xffffffffu, rs0, 2);
        rs1 += __shfl_xor_sync(0xffffffffu, rs1, 1);
        rs1 += __shfl_xor_sync(0xffffffffu, rs1, 2);
        lrow0 = lrow0 * cf0 + rs0;
        lrow1 = lrow1 * cf1 + rs1;
        #pragma unroll
        for (int df = 0; df < 8; df++) {
            Oa[df][0] *= cf0; Oa[df][1] *= cf0;
            Oa[df][2] *= cf1; Oa[df][3] *= cf1;
        }
        uint32_t pa[8][4];
        #pragma unroll
        for (int f = 0; f < 8; f++) {
            pa[f][0] = packbf(sacc[2 * f][0], sacc[2 * f][1]);
            pa[f][1] = packbf(sacc[2 * f][2], sacc[2 * f][3]);
            pa[f][2] = packbf(sacc[2 * f + 1][0], sacc[2 * f + 1][1]);
            pa[f][3] = packbf(sacc[2 * f + 1][2], sacc[2 * f + 1][3]);
        }

        // O += P V  (V already resident; no wait)
        #pragma unroll
        for (int f = 0; f < 8; f++) {
            #pragma unroll
            for (int q = 0; q < 4; q++) {
                uint32_t bv[4];
                ldsm4t(bv, sV + (uint32_t)((f * 16 + vKeyOff) * LQ + (vDSel + 2 * q) * 8) * 2);
                mma16816<false>(Oa[2 * q], pa[f], bv[0], bv[1]);
                mma16816<false>(Oa[2 * q + 1], pa[f], bv[2], bv[3]);
            }
        }
        __syncthreads();               // all warps done with K/V/mask[cur]
        if (kt + 2 < 8) {
            issueK(kt + 2);            // refill parity buffer
            issueV(kt + 2);
        }
    }

    float inv0 = 1.0f / lrow0, inv1 = 1.0f / lrow1;
    int orow = b * N_ + q0 + w * 16 + g;
    #pragma unroll
    for (int df = 0; df < 8; df++) {
        int col = h * 64 + df * 8 + 2 * tg;
        *(__nv_bfloat162*)(attn + (size_t)orow * 512 + col) =
            __floats2bfloat162_rn(Oa[df][0] * inv0, Oa[df][1] * inv0);
        *(__nv_bfloat162*)(attn + (size_t)(orow + 8) * 512 + col) =
            __floats2bfloat162_rn(Oa[df][2] * inv1, Oa[df][3] * inv1);
    }
}

// ---------------- att_topk + prune (round-6 proven) ----------------
__device__ __forceinline__ float blkmax(float v, float* red, int tid) {
    #pragma unroll
    for (int o = 16; o > 0; o >>= 1) v = fmaxf(v, __shfl_xor_sync(0xffffffffu, v, o));
    if ((tid & 31) == 0) red[tid >> 5] = v;
    __syncthreads();
    if (tid < 32) {
        float t = red[tid];
        #pragma unroll
        for (int o = 16; o > 0; o >>= 1) t = fmaxf(t, __shfl_xor_sync(0xffffffffu, t, o));
        if (tid == 0) red[0] = t;
    }
    __syncthreads();
    float r = red[0];
    __syncthreads();
    return r;
}
__device__ __forceinline__ float blksum(float v, float* red, int tid) {
    #pragma unroll
    for (int o = 16; o > 0; o >>= 1) v += __shfl_xor_sync(0xffffffffu, v, o);
    if ((tid & 31) == 0) red[tid >> 5] = v;
    __syncthreads();
    if (tid < 32) {
        float t = red[tid];
        #pragma unroll
        for (int o = 16; o > 0; o >>= 1) t += __shfl_xor_sync(0xffffffffu, t, o);
        if (tid == 0) red[0] = t;
    }
    __syncthreads();
    float r = red[0];
    __syncthreads();
    return r;
}
__global__ void __launch_bounds__(1024) topk0_kernel(const bf16* __restrict__ qkv,
                                                     const float* __restrict__ mask,
                                                     float* __restrict__ topk) {
    int b = blockIdx.x, m = threadIdx.x;
    __shared__ float q0s[512];
    __shared__ float red[32];
    size_t rb = (size_t)b * N_ * 1536;
    if (m < 512) q0s[m] = __bfloat162float(qkv[rb + m]);
    __syncthreads();
    const bf16* krow = qkv + rb + (size_t)m * 1536 + 512;
    float s[8];
    #pragma unroll
    for (int h = 0; h < 8; h++) {
        float acc = 0.0f;
        #pragma unroll
        for (int j = 0; j < 64; j += 8) {
            uint4 kv = *(const uint4*)(krow + h * 64 + j);
            bf16 t[8]; *(uint4*)t = kv;
            #pragma unroll
            for (int i = 0; i < 8; i++) acc += q0s[h * 64 + j + i] * __bfloat162float(t[i]);
        }
        s[h] = acc * 0.125f;
    }
    if (mask[(size_t)b * N_ * N_ + m] == 1.0f)
        #pragma unroll
        for (int h = 0; h < 8; h++) s[h] = NEGBIG;
    float out = 0.0f;
    #pragma unroll
    for (int h = 0; h < 8; h++) {
        float M = blkmax(s[h], red, m);
        float p = __expf(s[h] - M);
        float L = blksum(p, red, m);
        out += p / L;
    }
    topk[b * N_ + m] = out * 0.125f;
}

__global__ void __launch_bounds__(1024) prune_kernel(const float* __restrict__ topk,
                                                     float* __restrict__ out) {
    int b = blockIdx.x, m = threadIdx.x;
    __shared__ float key[N_];
    float km = (m == 0) ? NINF : topk[b * N_ + m];
    key[m] = km;
    __syncthreads();
    int rank = 0;
    for (int j = 0; j < N_; j++) {
        float kj = key[j];
        rank += (kj > km) || (kj == km && j < m);
    }
    if (rank >= 959 && rank < 1023) out[4194304 + b * 64 + (rank - 959)] = (float)m;
    if (m == 0) out[4194816 + b] = -1.0f;
    if (m < 16) out[4194824 + b * 16 + m] = 0.0f;
}

// ------- 16-bit GEMM, cp.async 2-stage, tile 128x128 (round-6 champion) -------
template<int EPI, bool HALF>
__global__ void __launch_bounds__(256) gemm_k(
    const uint16_t* __restrict__ A, const uint16_t* __restrict__ Bm, void* __restrict__ Cp,
    int K, int lda, int ldb, int ldc,
    const float* __restrict__ bias, const float* __restrict__ resid)
{
    constexpr int LA = 40, LB = 136;
    __shared__ uint16_t As[2][128 * LA];
    __shared__ uint16_t Bs[2][32 * LB];
    int tid = threadIdx.x, warp = tid >> 5, lane = tid & 31;
    int g = lane >> 2, tg = lane & 3;
    int warpM = warp & 3, warpN = warp >> 2;
    int row0 = blockIdx.y * 128, col0 = blockIdx.x * 128;
    uint32_t sA = (uint32_t)__cvta_generic_to_shared(As);
    uint32_t sB = (uint32_t)__cvta_generic_to_shared(Bs);
    int koff = ((lane >> 3) & 1) * 8 + (lane & 7);
    int nsel = (lane >> 4) * 8;

    float acc[2][8][4];
    #pragma unroll
    for (int a = 0; a < 2; a++)
        #pragma unroll
        for (int b2 = 0; b2 < 8; b2++)
            #pragma unroll
            for (int c = 0; c < 4; c++) acc[a][b2][c] = 0.0f;

    auto issue = [&](int st, int k0) {
        #pragma unroll
        for (int it = 0, c = tid; it < 2; it++, c += 256) {
            int r = c >> 2, kc = (c & 3) * 8;
            cp16(sA + (st * 128 * LA + r * LA + kc) * 2,
                 A + (size_t)(row0 + r) * lda + k0 + kc);
        }
        #pragma unroll
        for (int it = 0, c = tid; it < 2; it++, c += 256) {
            int kk = c >> 4, nc = (c & 15) * 8;
            cp16(sB + (st * 32 * LB + kk * LB + nc) * 2,
                 Bm + (size_t)(k0 + kk) * ldb + col0 + nc);
        }
        cpcommit();
    };

    issue(0, 0);
    int nk = K / 32;
    for (int i = 0; i < nk; i++) {
        int st = i & 1;
        cpwait0();
        __syncthreads();
        if (i + 1 < nk) issue(st ^ 1, (i + 1) * 32);
        const uint16_t* Ab = As[st];
        uint32_t sBst = sB + st * 32 * LB * 2;
        #pragma unroll
        for (int kk = 0; kk < 32; kk += 16) {
            uint32_t af[2][4];
            #pragma unroll
            for (int mt = 0; mt < 2; mt++) {
                const uint16_t* p = &Ab[(warpM * 32 + mt * 16 + g) * LA + kk + 2 * tg];
                af[mt][0] = *(const uint32_t*)p;
                af[mt][1] = *(const uint32_t*)(p + 8 * LA);
                af[mt][2] = *(const uint32_t*)(p + 8);
                af[mt][3] = *(const uint32_t*)(p + 8 * LA + 8);
            }
            #pragma unroll
            for (int p2 = 0; p2 < 4; p2++) {
                uint32_t bq[4];
                ldsm4t(bq, sBst + (uint32_t)((kk + koff) * LB + warpN * 64 + p2 * 16 + nsel) * 2);
                #pragma unroll
                for (int mt = 0; mt < 2; mt++) {
                    mma16816<HALF>(acc[mt][2 * p2], af[mt], bq[0], bq[1]);
                    mma16816<HALF>(acc[mt][2 * p2 + 1], af[mt], bq[2], bq[3]);
                }
            }
        }
        __syncthreads();
    }
    #pragma unroll
    for (int mt = 0; mt < 2; mt++)
        #pragma unroll
        for (int nt = 0; nt < 8; nt++) {
            int r = row0 + warpM * 32 + mt * 16 + g;
            int cc = col0 + warpN * 64 + nt * 8 + 2 * tg;
            #pragma unroll
            for (int hf = 0; hf < 2; hf++) {
                int rr = r + hf * 8;
                float v0 = acc[mt][nt][hf * 2], v1 = acc[mt][nt][hf * 2 + 1];
                long idx = (long)rr * ldc + cc;
                if (EPI == 2) {
                    v0 += bias[cc] + resid[idx];
                    v1 += bias[cc + 1] + resid[idx + 1];
                    *(float2*)((float*)Cp + idx) = make_float2(v0, v1);
                } else {
                    if (EPI == 3) {
                        v0 += bias[cc]; v1 += bias[cc + 1];
                        v0 = 0.5f * v0 * (1.0f + erff(v0 * 0.70710678f));
                        v1 = 0.5f * v1 * (1.0f + erff(v1 * 0.70710678f));
                    }
                    uint32_t pk;
                    if (HALF) { __half2 t = __floats2half2_rn(v0, v1); pk = *(uint32_t*)&t; }
                    else pk = packbf(v0, v1);
                    *(uint32_t*)((uint16_t*)Cp + idx) = pk;
                }
            }
        }
}

// ---------------- host ----------------
template <typename T>
static T* symaddr(const T& sym) {
    void* p = nullptr;
    cudaGetSymbolAddress(&p, sym);
    return (T*)p;
}

extern "C" void kernel_launch(void* const* d_in, const int* in_sizes, int n_in,
                              void* d_out, int out_size) {
    const float* x    = (const float*)d_in[0];
    const float* mask = (const float*)d_in[1];
    const float* Wqkv = (const float*)d_in[2];
    const float* Wout = (const float*)d_in[3];
    const float* bout = (const float*)d_in[4];
    const float* ln1g = (const float*)d_in[5];
    const float* ln1b = (const float*)d_in[6];
    const float* ln2g = (const float*)d_in[7];
    const float* ln2b = (const float*)d_in[8];
    const float* W1   = (const float*)d_in[9];
    const float* b1   = (const float*)d_in[10];
    const float* W2   = (const float*)d_in[11];
    const float* b2   = (const float*)d_in[12];

    bf16* h = (bf16*)symaddr(g_h);
    bf16* qkv = (bf16*)symaddr(g_qkv);
    bf16* attn = (bf16*)symaddr(g_attn);
    float* x1 = (float*)symaddr(g_x1);
    __half* h2h = (__half*)symaddr(g_h2h);
    __half* ffh = (__half*)symaddr(g_ffh);
    float* tk = (float*)symaddr(g_topk);
    uint32_t* mb = (uint32_t*)symaddr(g_mbits);
    bf16* wqkv = (bf16*)symaddr(g_Wqkv);
    bf16* wout = (bf16*)symaddr(g_Wout);
    __half* w1h = (__half*)symaddr(g_W1h);
    __half* w2h = (__half*)symaddr(g_W2h);

    cudaFuncSetAttribute(flash_kernel, cudaFuncAttributeMaxDynamicSharedMemorySize, FL_SMEM);

    cvtall_kernel<<<(NW1 + NW2 + NW3 + NW4 + 255) / 256, 256>>>(
        Wqkv, Wout, W1, W2, wqkv, wout, w1h, w2h);
    maskbits_kernel<<<B_ * N_ * N_ / 256, 256>>>(mask, mb);
    ln_kernel<0><<<ROWS_ / 8, 256>>>(x, ln1g, ln1b, h);

    gemm_k<0, false><<<dim3(12, 64), 256>>>(
        (const uint16_t*)h, (const uint16_t*)wqkv, qkv, D_, D_, 3 * D_, 3 * D_,
        nullptr, nullptr);
    flash_kernel<<<dim3(8, 64), 256, FL_SMEM>>>(qkv, mb, attn);
    topk0_kernel<<<B_, 1024>>>(qkv, mask, tk);
    prune_kernel<<<B_, 1024>>>(tk, (float*)d_out);
    gemm_k<2, false><<<dim3(4, 64), 256>>>(
        (const uint16_t*)attn, (const uint16_t*)wout, x1, D_, D_, D_, D_,
        bout, x);
    ln_kernel<1><<<ROWS_ / 8, 256>>>(x1, ln2g, ln2b, h2h);
    gemm_k<3, true><<<dim3(16, 64), 256>>>(
        (const uint16_t*)h2h, (const uint16_t*)w1h, ffh, D_, D_, MLP_, MLP_,
        b1, nullptr);
    gemm_k<2, true><<<dim3(4, 64), 256>>>(
        (const uint16_t*)ffh, (const uint16_t*)w2h, (float*)d_out, MLP_, MLP_, D_, D_,
        b2, x1);
}

// round 15
// speedup vs baseline: 1.4277x; 1.2033x over previous
#include <cuda_runtime.h>
#include <cuda_bf16.h>
#include <cuda_fp16.h>
#include <cstdint>

using bf16 = __nv_bfloat16;

#define B_ 8
#define N_ 1024
#define D_ 512
#define MLP_ 2048
#define ROWS_ (B_ * N_)
#define NEGBIG (-1e10f)
#define NINF __int_as_float(0xff800000)

// ---------------- scratch ----------------
__device__ bf16  g_h[ROWS_ * D_];
__device__ bf16  g_qkv[ROWS_ * 3 * D_];
__device__ bf16  g_attn[ROWS_ * D_];
__device__ float g_x1[ROWS_ * D_];
__device__ __half g_h2h[ROWS_ * D_];
__device__ __half g_ffh[ROWS_ * MLP_];
__device__ float g_topk[B_ * N_];
__device__ uint32_t g_mbits[B_ * N_ * 32];
__device__ bf16  g_Wqkv[D_ * 3 * D_];
__device__ bf16  g_Wout[D_ * D_];
__device__ __half g_W1h[D_ * MLP_];
__device__ __half g_W2h[MLP_ * D_];

// ---------------- helpers ----------------
template<bool HALF>
__device__ __forceinline__ void mma16816(float* c, const uint32_t* a, uint32_t b0, uint32_t b1) {
    if (HALF)
        asm volatile("mma.sync.aligned.m16n8k16.row.col.f32.f16.f16.f32 "
                     "{%0,%1,%2,%3},{%4,%5,%6,%7},{%8,%9},{%0,%1,%2,%3};\n"
                     : "+f"(c[0]), "+f"(c[1]), "+f"(c[2]), "+f"(c[3])
                     : "r"(a[0]), "r"(a[1]), "r"(a[2]), "r"(a[3]), "r"(b0), "r"(b1));
    else
        asm volatile("mma.sync.aligned.m16n8k16.row.col.f32.bf16.bf16.f32 "
                     "{%0,%1,%2,%3},{%4,%5,%6,%7},{%8,%9},{%0,%1,%2,%3};\n"
                     : "+f"(c[0]), "+f"(c[1]), "+f"(c[2]), "+f"(c[3])
                     : "r"(a[0]), "r"(a[1]), "r"(a[2]), "r"(a[3]), "r"(b0), "r"(b1));
}
__device__ __forceinline__ void ldsm4(uint32_t* r, uint32_t a) {
    asm volatile("ldmatrix.sync.aligned.m8n8.x4.shared.b16 {%0,%1,%2,%3},[%4];"
                 : "=r"(r[0]), "=r"(r[1]), "=r"(r[2]), "=r"(r[3]) : "r"(a));
}
__device__ __forceinline__ void ldsm4t(uint32_t* r, uint32_t a) {
    asm volatile("ldmatrix.sync.aligned.m8n8.x4.trans.shared.b16 {%0,%1,%2,%3},[%4];"
                 : "=r"(r[0]), "=r"(r[1]), "=r"(r[2]), "=r"(r[3]) : "r"(a));
}
__device__ __forceinline__ uint32_t packbf(float x, float y) {
    __nv_bfloat162 t = __floats2bfloat162_rn(x, y);
    return *(uint32_t*)&t;
}
__device__ __forceinline__ void cp16(uint32_t s, const void* g) {
    asm volatile("cp.async.cg.shared.global [%0],[%1],16;\n" :: "r"(s), "l"(g));
}
__device__ __forceinline__ void cp4(uint32_t s, const void* g) {
    asm volatile("cp.async.ca.shared.global [%0],[%1],4;\n" :: "r"(s), "l"(g));
}
__device__ __forceinline__ void cpcommit() { asm volatile("cp.async.commit_group;\n"); }
__device__ __forceinline__ void cpwait0() { asm volatile("cp.async.wait_group 0;\n"); }
__device__ __forceinline__ void cpwait2() { asm volatile("cp.async.wait_group 2;\n"); }

// ---------------- fused weight convert ----------------
#define NW1 786432
#define NW2 262144
#define NW3 1048576
#define NW4 1048576
__global__ void cvtall_kernel(const float* __restrict__ wqkv, const float* __restrict__ wout,
                              const float* __restrict__ w1, const float* __restrict__ w2,
                              bf16* __restrict__ dqkv, bf16* __restrict__ dout,
                              __half* __restrict__ d1, __half* __restrict__ d2) {
    int i = blockIdx.x * blockDim.x + threadIdx.x;
    if (i < NW1) { dqkv[i] = __float2bfloat16(wqkv[i]); return; }
    i -= NW1;
    if (i < NW2) { dout[i] = __float2bfloat16(wout[i]); return; }
    i -= NW2;
    if (i < NW3) { d1[i] = __float2half_rn(w1[i]); return; }
    i -= NW3;
    if (i < NW4) { d2[i] = __float2half_rn(w2[i]); }
}

__global__ void maskbits_kernel(const float* __restrict__ mask, uint32_t* __restrict__ bits) {
    int idx = blockIdx.x * blockDim.x + threadIdx.x;
    uint32_t bal = __ballot_sync(0xffffffffu, mask[idx] == 1.0f);
    if ((idx & 31) == 0) bits[idx >> 5] = bal;
}

// ---------------- LayerNorm: warp-per-row, 8 rows/CTA. OUT: 0=bf16, 1=fp16 ------
template<int OUT>
__global__ void __launch_bounds__(256) ln_kernel(const float* __restrict__ x,
                                                 const float* __restrict__ gam,
                                                 const float* __restrict__ bet,
                                                 void* __restrict__ out) {
    int w = threadIdx.x >> 5, lane = threadIdx.x & 31;
    size_t row = (size_t)blockIdx.x * 8 + w;
    const float4* xr = (const float4*)(x + row * D_);
    float4 v[4];
    float s = 0.0f, sq = 0.0f;
    #pragma unroll
    for (int i = 0; i < 4; i++) {
        v[i] = xr[lane + i * 32];
        s  += v[i].x + v[i].y + v[i].z + v[i].w;
        sq += v[i].x * v[i].x + v[i].y * v[i].y + v[i].z * v[i].z + v[i].w * v[i].w;
    }
    #pragma unroll
    for (int o = 16; o > 0; o >>= 1) {
        s  += __shfl_xor_sync(0xffffffffu, s, o);
        sq += __shfl_xor_sync(0xffffffffu, sq, o);
    }
    float mu = s * (1.0f / D_);
    float rs = rsqrtf(sq * (1.0f / D_) - mu * mu + 1e-5f);
    #pragma unroll
    for (int i = 0; i < 4; i++) {
        int fi = lane + i * 32;
        float4 gv = ((const float4*)gam)[fi];
        float4 bv = ((const float4*)bet)[fi];
        float o0 = (v[i].x - mu) * rs * gv.x + bv.x;
        float o1 = (v[i].y - mu) * rs * gv.y + bv.y;
        float o2 = (v[i].z - mu) * rs * gv.z + bv.z;
        float o3 = (v[i].w - mu) * rs * gv.w + bv.w;
        if (OUT == 0) {
            bf16* o = (bf16*)out + row * D_ + fi * 4;
            ((__nv_bfloat162*)o)[0] = __floats2bfloat162_rn(o0, o1);
            ((__nv_bfloat162*)o)[1] = __floats2bfloat162_rn(o2, o3);
        } else {
            __half* o = (__half*)out + row * D_ + fi * 4;
            ((__half2*)o)[0] = __floats2half2_rn(o0, o1);
            ((__half2*)o)[1] = __floats2half2_rn(o2, o3);
        }
    }
}

// ------- flash attention: 2-deep K/V ring (R14 champion) -----
#define LQ 72
#define FTILE (128 * LQ * 2)
#define FL_SMEM (5 * FTILE + 2 * 512 * 4)
__global__ void __launch_bounds__(256, 2) flash_kernel(const bf16* __restrict__ qkv,
                                                       const uint32_t* __restrict__ mbits,
                                                       bf16* __restrict__ attn) {
    extern __shared__ char sm[];
    uint32_t sQ = (uint32_t)__cvta_generic_to_shared(sm);
    uint32_t sKb[2] = {sQ + FTILE, sQ + 2 * FTILE};
    uint32_t sVb[2] = {sQ + 3 * FTILE, sQ + 4 * FTILE};
    uint32_t* mw = (uint32_t*)(sm + 5 * FTILE);

    int bh = blockIdx.y, b = bh >> 3, h = bh & 7;
    int tid = threadIdx.x, w = tid >> 5, lane = tid & 31, g = lane >> 2, tg = lane & 3;
    int q0 = blockIdx.x * 128;
    size_t base = (size_t)b * N_ * 1536;

    auto issueK = [&](int kt) {
        uint32_t dst = sKb[kt & 1];
        #pragma unroll
        for (int it = 0, c = tid; it < 4; it++, c += 256) {
            int r = c >> 3, d0 = (c & 7) * 8;
            cp16(dst + (r * LQ + d0) * 2,
                 qkv + base + (size_t)(kt * 128 + r) * 1536 + 512 + h * 64 + d0);
        }
        uint32_t sMW = sQ + 5 * FTILE + (uint32_t)((kt & 1) * 512) * 4;
        #pragma unroll
        for (int it = 0, c = tid; it < 2; it++, c += 256)
            cp4(sMW + c * 4, &mbits[((size_t)b * N_ + q0 + (c >> 2)) * 32 + kt * 4 + (c & 3)]);
        cpcommit();
    };
    auto issueV = [&](int kt) {
        uint32_t dst = sVb[kt & 1];
        #pragma unroll
        for (int it = 0, c = tid; it < 4; it++, c += 256) {
            int r = c >> 3, d0 = (c & 7) * 8;
            cp16(dst + (r * LQ + d0) * 2,
                 qkv + base + (size_t)(kt * 128 + r) * 1536 + 1024 + h * 64 + d0);
        }
        cpcommit();
    };

    #pragma unroll
    for (int it = 0, c = tid; it < 4; it++, c += 256) {
        int r = c >> 3, d0 = (c & 7) * 8;
        cp16(sQ + (r * LQ + d0) * 2, qkv + base + (size_t)(q0 + r) * 1536 + h * 64 + d0);
    }
    issueK(0);
    issueV(0);
    issueK(1);
    issueV(1);

    float Oa[8][4];
    #pragma unroll
    for (int i = 0; i < 8; i++)
        #pragma unroll
        for (int j = 0; j < 4; j++) Oa[i][j] = 0.0f;
    float mrow0 = NINF, mrow1 = NINF, lrow0 = 0.0f, lrow1 = 0.0f;

    int aRow = w * 16 + ((lane >> 3) & 1) * 8 + (lane & 7);
    int aSel = (lane >> 4) * 8;
    int bRowOff = (lane >> 4) * 8 + (lane & 7);
    int bSel = ((lane >> 3) & 1) * 8;
    int vKeyOff = ((lane >> 3) & 1) * 8 + (lane & 7);
    int vDSel = (lane >> 4);

    for (int kt = 0; kt < 8; kt++) {
        int cur = kt & 1;
        if (kt < 7) cpwait2(); else cpwait0();
        __syncthreads();

        uint32_t sK = sKb[cur], sV = sVb[cur];
        float sacc[16][4];
        #pragma unroll
        for (int nf = 0; nf < 16; nf++)
            #pragma unroll
            for (int j = 0; j < 4; j++) sacc[nf][j] = 0.0f;
        #pragma unroll
        for (int kk = 0; kk < 64; kk += 16) {
            uint32_t aq[4];
            ldsm4(aq, sQ + (uint32_t)(aRow * LQ + kk + aSel) * 2);
            #pragma unroll
            for (int nfp = 0; nfp < 8; nfp++) {
                uint32_t bq[4];
                ldsm4(bq, sK + (uint32_t)((nfp * 16 + bRowOff) * LQ + kk + bSel) * 2);
                mma16816<false>(sacc[2 * nfp], aq, bq[0], bq[1]);
                mma16816<false>(sacc[2 * nfp + 1], aq, bq[2], bq[3]);
            }
        }

        int r0l = w * 16 + g;
        uint32_t mwa[4], mwb[4];
        #pragma unroll
        for (int i = 0; i < 4; i++) {
            mwa[i] = mw[cur * 512 + r0l * 4 + i];
            mwb[i] = mw[cur * 512 + (r0l + 8) * 4 + i];
        }
        float mx0 = -3e38f, mx1 = -3e38f;
        #pragma unroll
        for (int nf = 0; nf < 16; nf++) {
            int c0 = nf * 8 + 2 * tg;
            uint32_t wa = mwa[c0 >> 5], wb = mwb[c0 >> 5];
            int shm = c0 & 31;
            float s00 = ((wa >> shm) & 1) ? NEGBIG : sacc[nf][0] * 0.125f;
            float s01 = ((wa >> (shm + 1)) & 1) ? NEGBIG : sacc[nf][1] * 0.125f;
            float s10 = ((wb >> shm) & 1) ? NEGBIG : sacc[nf][2] * 0.125f;
            float s11 = ((wb >> (shm + 1)) & 1) ? NEGBIG : sacc[nf][3] * 0.125f;
            sacc[nf][0] = s00; sacc[nf][1] = s01; sacc[nf][2] = s10; sacc[nf][3] = s11;
            mx0 = fmaxf(mx0, fmaxf(s00, s01));
            mx1 = fmaxf(mx1, fmaxf(s10, s11));
        }
        mx0 = fmaxf(mx0, __shfl_xor_sync(0xffffffffu, mx0, 1));
        mx0 = fmaxf(mx0, __shfl_xor_sync(0xffffffffu, mx0, 2));
        mx1 = fmaxf(mx1, __shfl_xor_sync(0xffffffffu, mx1, 1));
        mx1 = fmaxf(mx1, __shfl_xor_sync(0xffffffffu, mx1, 2));
        float mn0 = fmaxf(mrow0, mx0), mn1 = fmaxf(mrow1, mx1);
        float cf0 = __expf(mrow0 - mn0), cf1 = __expf(mrow1 - mn1);
        mrow0 = mn0; mrow1 = mn1;
        float rs0 = 0.0f, rs1 = 0.0f;
        #pragma unroll
        for (int nf = 0; nf < 16; nf++) {
            float p00 = __expf(sacc[nf][0] - mn0);
            float p01 = __expf(sacc[nf][1] - mn0);
            float p10 = __expf(sacc[nf][2] - mn1);
            float p11 = __expf(sacc[nf][3] - mn1);
            sacc[nf][0] = p00; sacc[nf][1] = p01; sacc[nf][2] = p10; sacc[nf][3] = p11;
            rs0 += p00 + p01; rs1 += p10 + p11;
        }
        rs0 += __shfl_xor_sync(0xffffffffu, rs0, 1);
        rs0 += __shfl_xor_sync(0xffffffffu, rs0, 2);
        rs1 += __shfl_xor_sync(0xffffffffu, rs1, 1);
        rs1 += __shfl_xor_sync(0xffffffffu, rs1, 2);
        lrow0 = lrow0 * cf0 + rs0;
        lrow1 = lrow1 * cf1 + rs1;
        #pragma unroll
        for (int df = 0; df < 8; df++) {
            Oa[df][0] *= cf0; Oa[df][1] *= cf0;
            Oa[df][2] *= cf1; Oa[df][3] *= cf1;
        }
        uint32_t pa[8][4];
        #pragma unroll
        for (int f = 0; f < 8; f++) {
            pa[f][0] = packbf(sacc[2 * f][0], sacc[2 * f][1]);
            pa[f][1] = packbf(sacc[2 * f][2], sacc[2 * f][3]);
            pa[f][2] = packbf(sacc[2 * f + 1][0], sacc[2 * f + 1][1]);
            pa[f][3] = packbf(sacc[2 * f + 1][2], sacc[2 * f + 1][3]);
        }

        #pragma unroll
        for (int f = 0; f < 8; f++) {
            #pragma unroll
            for (int q = 0; q < 4; q++) {
                uint32_t bv[4];
                ldsm4t(bv, sV + (uint32_t)((f * 16 + vKeyOff) * LQ + (vDSel + 2 * q) * 8) * 2);
                mma16816<false>(Oa[2 * q], pa[f], bv[0], bv[1]);
                mma16816<false>(Oa[2 * q + 1], pa[f], bv[2], bv[3]);
            }
        }
        __syncthreads();
        if (kt + 2 < 8) {
            issueK(kt + 2);
            issueV(kt + 2);
        }
    }

    float inv0 = 1.0f / lrow0, inv1 = 1.0f / lrow1;
    int orow = b * N_ + q0 + w * 16 + g;
    #pragma unroll
    for (int df = 0; df < 8; df++) {
        int col = h * 64 + df * 8 + 2 * tg;
        *(__nv_bfloat162*)(attn + (size_t)orow * 512 + col) =
            __floats2bfloat162_rn(Oa[df][0] * inv0, Oa[df][1] * inv0);
        *(__nv_bfloat162*)(attn + (size_t)(orow + 8) * 512 + col) =
            __floats2bfloat162_rn(Oa[df][2] * inv1, Oa[df][3] * inv1);
    }
}

// ---------------- att_topk + prune ----------------
__device__ __forceinline__ float blkmax(float v, float* red, int tid) {
    #pragma unroll
    for (int o = 16; o > 0; o >>= 1) v = fmaxf(v, __shfl_xor_sync(0xffffffffu, v, o));
    if ((tid & 31) == 0) red[tid >> 5] = v;
    __syncthreads();
    if (tid < 32) {
        float t = red[tid];
        #pragma unroll
        for (int o = 16; o > 0; o >>= 1) t = fmaxf(t, __shfl_xor_sync(0xffffffffu, t, o));
        if (tid == 0) red[0] = t;
    }
    __syncthreads();
    float r = red[0];
    __syncthreads();
    return r;
}
__device__ __forceinline__ float blksum(float v, float* red, int tid) {
    #pragma unroll
    for (int o = 16; o > 0; o >>= 1) v += __shfl_xor_sync(0xffffffffu, v, o);
    if ((tid & 31) == 0) red[tid >> 5] = v;
    __syncthreads();
    if (tid < 32) {
        float t = red[tid];
        #pragma unroll
        for (int o = 16; o > 0; o >>= 1) t += __shfl_xor_sync(0xffffffffu, t, o);
        if (tid == 0) red[0] = t;
    }
    __syncthreads();
    float r = red[0];
    __syncthreads();
    return r;
}
__global__ void __launch_bounds__(1024) topk0_kernel(const bf16* __restrict__ qkv,
                                                     const float* __restrict__ mask,
                                                     float* __restrict__ topk) {
    int b = blockIdx.x, m = threadIdx.x;
    __shared__ float q0s[512];
    __shared__ float red[32];
    size_t rb = (size_t)b * N_ * 1536;
    if (m < 512) q0s[m] = __bfloat162float(qkv[rb + m]);
    __syncthreads();
    const bf16* krow = qkv + rb + (size_t)m * 1536 + 512;
    float s[8];
    #pragma unroll
    for (int h = 0; h < 8; h++) {
        float acc = 0.0f;
        #pragma unroll
        for (int j = 0; j < 64; j += 8) {
            uint4 kv = *(const uint4*)(krow + h * 64 + j);
            bf16 t[8]; *(uint4*)t = kv;
            #pragma unroll
            for (int i = 0; i < 8; i++) acc += q0s[h * 64 + j + i] * __bfloat162float(t[i]);
        }
        s[h] = acc * 0.125f;
    }
    if (mask[(size_t)b * N_ * N_ + m] == 1.0f)
        #pragma unroll
        for (int h = 0; h < 8; h++) s[h] = NEGBIG;
    float out = 0.0f;
    #pragma unroll
    for (int h = 0; h < 8; h++) {
        float M = blkmax(s[h], red, m);
        float p = __expf(s[h] - M);
        float L = blksum(p, red, m);
        out += p / L;
    }
    topk[b * N_ + m] = out * 0.125f;
}

__global__ void __launch_bounds__(1024) prune_kernel(const float* __restrict__ topk,
                                                     float* __restrict__ out) {
    int b = blockIdx.x, m = threadIdx.x;
    __shared__ float key[N_];
    float km = (m == 0) ? NINF : topk[b * N_ + m];
    key[m] = km;
    __syncthreads();
    int rank = 0;
    for (int j = 0; j < N_; j++) {
        float kj = key[j];
        rank += (kj > km) || (kj == km && j < m);
    }
    if (rank >= 959 && rank < 1023) out[4194304 + b * 64 + (rank - 959)] = (float)m;
    if (m == 0) out[4194816 + b] = -1.0f;
    if (m < 16) out[4194824 + b * 16 + m] = 0.0f;
}

// ------- 16-bit GEMM, cp.async 2-stage, tile 128x128 -------
template<int EPI, bool HALF>
__global__ void __launch_bounds__(256) gemm_k(
    const uint16_t* __restrict__ A, const uint16_t* __restrict__ Bm, void* __restrict__ Cp,
    int K, int lda, int ldb, int ldc,
    const float* __restrict__ bias, const float* __restrict__ resid)
{
    constexpr int LA = 40, LB = 136;
    __shared__ uint16_t As[2][128 * LA];
    __shared__ uint16_t Bs[2][32 * LB];
    int tid = threadIdx.x, warp = tid >> 5, lane = tid & 31;
    int g = lane >> 2, tg = lane & 3;
    int warpM = warp & 3, warpN = warp >> 2;
    int row0 = blockIdx.y * 128, col0 = blockIdx.x * 128;
    uint32_t sA = (uint32_t)__cvta_generic_to_shared(As);
    uint32_t sB = (uint32_t)__cvta_generic_to_shared(Bs);
    int koff = ((lane >> 3) & 1) * 8 + (lane & 7);
    int nsel = (lane >> 4) * 8;

    float acc[2][8][4];
    #pragma unroll
    for (int a = 0; a < 2; a++)
        #pragma unroll
        for (int b2 = 0; b2 < 8; b2++)
            #pragma unroll
            for (int c = 0; c < 4; c++) acc[a][b2][c] = 0.0f;

    auto issue = [&](int st, int k0) {
        #pragma unroll
        for (int it = 0, c = tid; it < 2; it++, c += 256) {
            int r = c >> 2, kc = (c & 3) * 8;
            cp16(sA + (st * 128 * LA + r * LA + kc) * 2,
                 A + (size_t)(row0 + r) * lda + k0 + kc);
        }
        #pragma unroll
        for (int it = 0, c = tid; it < 2; it++, c += 256) {
            int kk = c >> 4, nc = (c & 15) * 8;
            cp16(sB + (st * 32 * LB + kk * LB + nc) * 2,
                 Bm + (size_t)(k0 + kk) * ldb + col0 + nc);
        }
        cpcommit();
    };

    issue(0, 0);
    int nk = K / 32;
    for (int i = 0; i < nk; i++) {
        int st = i & 1;
        cpwait0();
        __syncthreads();
        if (i + 1 < nk) issue(st ^ 1, (i + 1) * 32);
        const uint16_t* Ab = As[st];
        uint32_t sBst = sB + st * 32 * LB * 2;
        #pragma unroll
        for (int kk = 0; kk < 32; kk += 16) {
            uint32_t af[2][4];
            #pragma unroll
            for (int mt = 0; mt < 2; mt++) {
                const uint16_t* p = &Ab[(warpM * 32 + mt * 16 + g) * LA + kk + 2 * tg];
                af[mt][0] = *(const uint32_t*)p;
                af[mt][1] = *(const uint32_t*)(p + 8 * LA);
                af[mt][2] = *(const uint32_t*)(p + 8);
                af[mt][3] = *(const uint32_t*)(p + 8 * LA + 8);
            }
            #pragma unroll
            for (int p2 = 0; p2 < 4; p2++) {
                uint32_t bq[4];
                ldsm4t(bq, sBst + (uint32_t)((kk + koff) * LB + warpN * 64 + p2 * 16 + nsel) * 2);
                #pragma unroll
                for (int mt = 0; mt < 2; mt++) {
                    mma16816<HALF>(acc[mt][2 * p2], af[mt], bq[0], bq[1]);
                    mma16816<HALF>(acc[mt][2 * p2 + 1], af[mt], bq[2], bq[3]);
                }
            }
        }
        __syncthreads();
    }
    #pragma unroll
    for (int mt = 0; mt < 2; mt++)
        #pragma unroll
        for (int nt = 0; nt < 8; nt++) {
            int r = row0 + warpM * 32 + mt * 16 + g;
            int cc = col0 + warpN * 64 + nt * 8 + 2 * tg;
            #pragma unroll
            for (int hf = 0; hf < 2; hf++) {
                int rr = r + hf * 8;
                float v0 = acc[mt][nt][hf * 2], v1 = acc[mt][nt][hf * 2 + 1];
                long idx = (long)rr * ldc + cc;
                if (EPI == 2) {
                    v0 += bias[cc] + resid[idx];
                    v1 += bias[cc + 1] + resid[idx + 1];
                    *(float2*)((float*)Cp + idx) = make_float2(v0, v1);
                } else {
                    if (EPI == 3) {
                        v0 += bias[cc]; v1 += bias[cc + 1];
                        v0 = 0.5f * v0 * (1.0f + erff(v0 * 0.70710678f));
                        v1 = 0.5f * v1 * (1.0f + erff(v1 * 0.70710678f));
                    }
                    uint32_t pk;
                    if (HALF) { __half2 t = __floats2half2_rn(v0, v1); pk = *(uint32_t*)&t; }
                    else pk = packbf(v0, v1);
                    *(uint32_t*)((uint16_t*)Cp + idx) = pk;
                }
            }
        }
}

// ---------------- host ----------------
template <typename T>
static T* symaddr(const T& sym) {
    void* p = nullptr;
    cudaGetSymbolAddress(&p, sym);
    return (T*)p;
}

extern "C" void kernel_launch(void* const* d_in, const int* in_sizes, int n_in,
                              void* d_out, int out_size) {
    const float* x    = (const float*)d_in[0];
    const float* mask = (const float*)d_in[1];
    const float* Wqkv = (const float*)d_in[2];
    const float* Wout = (const float*)d_in[3];
    const float* bout = (const float*)d_in[4];
    const float* ln1g = (const float*)d_in[5];
    const float* ln1b = (const float*)d_in[6];
    const float* ln2g = (const float*)d_in[7];
    const float* ln2b = (const float*)d_in[8];
    const float* W1   = (const float*)d_in[9];
    const float* b1   = (const float*)d_in[10];
    const float* W2   = (const float*)d_in[11];
    const float* b2   = (const float*)d_in[12];

    bf16* h = (bf16*)symaddr(g_h);
    bf16* qkv = (bf16*)symaddr(g_qkv);
    bf16* attn = (bf16*)symaddr(g_attn);
    float* x1 = (float*)symaddr(g_x1);
    __half* h2h = (__half*)symaddr(g_h2h);
    __half* ffh = (__half*)symaddr(g_ffh);
    float* tk = (float*)symaddr(g_topk);
    uint32_t* mb = (uint32_t*)symaddr(g_mbits);
    bf16* wqkv = (bf16*)symaddr(g_Wqkv);
    bf16* wout = (bf16*)symaddr(g_Wout);
    __half* w1h = (__half*)symaddr(g_W1h);
    __half* w2h = (__half*)symaddr(g_W2h);

    // one-time (first, uncaptured call) stream/event creation — no device memory
    static cudaStream_t s1 = nullptr;
    static cudaEvent_t evA = nullptr, evB = nullptr, evC = nullptr, evD = nullptr;
    if (s1 == nullptr) {
        cudaStreamCreateWithFlags(&s1, cudaStreamNonBlocking);
        cudaEventCreateWithFlags(&evA, cudaEventDisableTiming);
        cudaEventCreateWithFlags(&evB, cudaEventDisableTiming);
        cudaEventCreateWithFlags(&evC, cudaEventDisableTiming);
        cudaEventCreateWithFlags(&evD, cudaEventDisableTiming);
        cudaFuncSetAttribute(flash_kernel, cudaFuncAttributeMaxDynamicSharedMemorySize, FL_SMEM);
    }

    // fork: maskbits on s1, overlapping cvtall + ln1 + qkv GEMM on main stream
    cudaEventRecord(evA, 0);
    cudaStreamWaitEvent(s1, evA, 0);
    maskbits_kernel<<<B_ * N_ * N_ / 256, 256, 0, s1>>>(mask, mb);
    cudaEventRecord(evB, s1);

    cvtall_kernel<<<(NW1 + NW2 + NW3 + NW4 + 255) / 256, 256>>>(
        Wqkv, Wout, W1, W2, wqkv, wout, w1h, w2h);
    ln_kernel<0><<<ROWS_ / 8, 256>>>(x, ln1g, ln1b, h);
    gemm_k<0, false><<<dim3(12, 64), 256>>>(
        (const uint16_t*)h, (const uint16_t*)wqkv, qkv, D_, D_, 3 * D_, 3 * D_,
        nullptr, nullptr);

    // fork: topk0 + prune on s1 (needs qkv), overlapping flash on main stream
    cudaEventRecord(evC, 0);
    cudaStreamWaitEvent(s1, evC, 0);
    topk0_kernel<<<B_, 1024, 0, s1>>>(qkv, mask, tk);
    prune_kernel<<<B_, 1024, 0, s1>>>(tk, (float*)d_out);
    cudaEventRecord(evD, s1);

    // main: flash waits on maskbits
    cudaStreamWaitEvent(0, evB, 0);
    flash_kernel<<<dim3(8, 64), 256, FL_SMEM>>>(qkv, mb, attn);
    gemm_k<2, false><<<dim3(4, 64), 256>>>(
        (const uint16_t*)attn, (const uint16_t*)wout, x1, D_, D_, D_, D_,
        bout, x);
    ln_kernel<1><<<ROWS_ / 8, 256>>>(x1, ln2g, ln2b, h2h);
    gemm_k<3, true><<<dim3(16, 64), 256>>>(
        (const uint16_t*)h2h, (const uint16_t*)w1h, ffh, D_, D_, MLP_, MLP_,
        b1, nullptr);
    gemm_k<2, true><<<dim3(4, 64), 256>>>(
        (const uint16_t*)ffh, (const uint16_t*)w2h, (float*)d_out, MLP_, MLP_, D_, D_,
        b2, x1);

    // join: prune's d_out writes complete before graph end
    cudaStreamWaitEvent(0, evD, 0);
}

// round 16
// speedup vs baseline: 1.4417x; 1.0098x over previous
#include <cuda_runtime.h>
#include <cuda_bf16.h>
#include <cuda_fp16.h>
#include <cstdint>

#define B_ 8
#define N_ 1024
#define D_ 512
#define MLP_ 2048
#define ROWS_ (B_ * N_)
#define NEGBIG (-1e10f)
#define NINF __int_as_float(0xff800000)

// ---------------- scratch (all activations fp16) ----------------
__device__ __half g_h[ROWS_ * D_];
__device__ __half g_qkv[ROWS_ * 3 * D_];
__device__ __half g_attn[ROWS_ * D_];
__device__ float  g_x1[ROWS_ * D_];
__device__ __half g_h2h[ROWS_ * D_];
__device__ __half g_ffh[ROWS_ * MLP_];
__device__ float  g_topk[B_ * N_];
__device__ uint32_t g_mbits[B_ * N_ * 32];
__device__ __half g_Wqkvh[D_ * 3 * D_];
__device__ __half g_Wouth[D_ * D_];
__device__ __half g_W1h[D_ * MLP_];
__device__ __half g_W2h[MLP_ * D_];

// ---------------- helpers ----------------
__device__ __forceinline__ void mmaf16(float* c, const uint32_t* a, uint32_t b0, uint32_t b1) {
    asm volatile("mma.sync.aligned.m16n8k16.row.col.f32.f16.f16.f32 "
                 "{%0,%1,%2,%3},{%4,%5,%6,%7},{%8,%9},{%0,%1,%2,%3};\n"
                 : "+f"(c[0]), "+f"(c[1]), "+f"(c[2]), "+f"(c[3])
                 : "r"(a[0]), "r"(a[1]), "r"(a[2]), "r"(a[3]), "r"(b0), "r"(b1));
}
__device__ __forceinline__ void ldsm4(uint32_t* r, uint32_t a) {
    asm volatile("ldmatrix.sync.aligned.m8n8.x4.shared.b16 {%0,%1,%2,%3},[%4];"
                 : "=r"(r[0]), "=r"(r[1]), "=r"(r[2]), "=r"(r[3]) : "r"(a));
}
__device__ __forceinline__ void ldsm4t(uint32_t* r, uint32_t a) {
    asm volatile("ldmatrix.sync.aligned.m8n8.x4.trans.shared.b16 {%0,%1,%2,%3},[%4];"
                 : "=r"(r[0]), "=r"(r[1]), "=r"(r[2]), "=r"(r[3]) : "r"(a));
}
__device__ __forceinline__ uint32_t packh(float x, float y) {
    __half2 t = __floats2half2_rn(x, y);
    return *(uint32_t*)&t;
}
__device__ __forceinline__ void cp16(uint32_t s, const void* g) {
    asm volatile("cp.async.cg.shared.global [%0],[%1],16;\n" :: "r"(s), "l"(g));
}
__device__ __forceinline__ void cp4(uint32_t s, const void* g) {
    asm volatile("cp.async.ca.shared.global [%0],[%1],4;\n" :: "r"(s), "l"(g));
}
__device__ __forceinline__ void cpcommit() { asm volatile("cp.async.commit_group;\n"); }
__device__ __forceinline__ void cpwait0() { asm volatile("cp.async.wait_group 0;\n"); }
__device__ __forceinline__ void cpwait2() { asm volatile("cp.async.wait_group 2;\n"); }

// ---------------- fp32 -> fp16 convert ----------------
__global__ void cvth_kernel(const float* __restrict__ s, __half* __restrict__ d, int n) {
    int i = blockIdx.x * blockDim.x + threadIdx.x;
    if (i < n) d[i] = __float2half_rn(s[i]);
}

__global__ void maskbits_kernel(const float* __restrict__ mask, uint32_t* __restrict__ bits) {
    int idx = blockIdx.x * blockDim.x + threadIdx.x;
    uint32_t bal = __ballot_sync(0xffffffffu, mask[idx] == 1.0f);
    if ((idx & 31) == 0) bits[idx >> 5] = bal;
}

// ---------------- LayerNorm: warp-per-row, 8 rows/CTA, fp16 out ----------------
__global__ void __launch_bounds__(256) ln_kernel(const float* __restrict__ x,
                                                 const float* __restrict__ gam,
                                                 const float* __restrict__ bet,
                                                 __half* __restrict__ out) {
    int w = threadIdx.x >> 5, lane = threadIdx.x & 31;
    size_t row = (size_t)blockIdx.x * 8 + w;
    const float4* xr = (const float4*)(x + row * D_);
    float4 v[4];
    float s = 0.0f, sq = 0.0f;
    #pragma unroll
    for (int i = 0; i < 4; i++) {
        v[i] = xr[lane + i * 32];
        s  += v[i].x + v[i].y + v[i].z + v[i].w;
        sq += v[i].x * v[i].x + v[i].y * v[i].y + v[i].z * v[i].z + v[i].w * v[i].w;
    }
    #pragma unroll
    for (int o = 16; o > 0; o >>= 1) {
        s  += __shfl_xor_sync(0xffffffffu, s, o);
        sq += __shfl_xor_sync(0xffffffffu, sq, o);
    }
    float mu = s * (1.0f / D_);
    float rs = rsqrtf(sq * (1.0f / D_) - mu * mu + 1e-5f);
    #pragma unroll
    for (int i = 0; i < 4; i++) {
        int fi = lane + i * 32;
        float4 gv = ((const float4*)gam)[fi];
        float4 bv = ((const float4*)bet)[fi];
        __half* o = out + row * D_ + fi * 4;
        ((__half2*)o)[0] = __floats2half2_rn((v[i].x - mu) * rs * gv.x + bv.x,
                                             (v[i].y - mu) * rs * gv.y + bv.y);
        ((__half2*)o)[1] = __floats2half2_rn((v[i].z - mu) * rs * gv.z + bv.z,
                                             (v[i].w - mu) * rs * gv.w + bv.w);
    }
}

// ------- flash attention: fp16, 2-deep K/V ring (R14/R15 structure) -----
#define LQ 72
#define FTILE (128 * LQ * 2)
#define FL_SMEM (5 * FTILE + 2 * 512 * 4)
__global__ void __launch_bounds__(256, 2) flash_kernel(const __half* __restrict__ qkv,
                                                       const uint32_t* __restrict__ mbits,
                                                       __half* __restrict__ attn) {
    extern __shared__ char sm[];
    uint32_t sQ = (uint32_t)__cvta_generic_to_shared(sm);
    uint32_t sKb[2] = {sQ + FTILE, sQ + 2 * FTILE};
    uint32_t sVb[2] = {sQ + 3 * FTILE, sQ + 4 * FTILE};
    uint32_t* mw = (uint32_t*)(sm + 5 * FTILE);

    int bh = blockIdx.y, b = bh >> 3, h = bh & 7;
    int tid = threadIdx.x, w = tid >> 5, lane = tid & 31, g = lane >> 2, tg = lane & 3;
    int q0 = blockIdx.x * 128;
    size_t base = (size_t)b * N_ * 1536;

    auto issueK = [&](int kt) {
        uint32_t dst = sKb[kt & 1];
        #pragma unroll
        for (int it = 0, c = tid; it < 4; it++, c += 256) {
            int r = c >> 3, d0 = (c & 7) * 8;
            cp16(dst + (r * LQ + d0) * 2,
                 qkv + base + (size_t)(kt * 128 + r) * 1536 + 512 + h * 64 + d0);
        }
        uint32_t sMW = sQ + 5 * FTILE + (uint32_t)((kt & 1) * 512) * 4;
        #pragma unroll
        for (int it = 0, c = tid; it < 2; it++, c += 256)
            cp4(sMW + c * 4, &mbits[((size_t)b * N_ + q0 + (c >> 2)) * 32 + kt * 4 + (c & 3)]);
        cpcommit();
    };
    auto issueV = [&](int kt) {
        uint32_t dst = sVb[kt & 1];
        #pragma unroll
        for (int it = 0, c = tid; it < 4; it++, c += 256) {
            int r = c >> 3, d0 = (c & 7) * 8;
            cp16(dst + (r * LQ + d0) * 2,
                 qkv + base + (size_t)(kt * 128 + r) * 1536 + 1024 + h * 64 + d0);
        }
        cpcommit();
    };

    #pragma unroll
    for (int it = 0, c = tid; it < 4; it++, c += 256) {
        int r = c >> 3, d0 = (c & 7) * 8;
        cp16(sQ + (r * LQ + d0) * 2, qkv + base + (size_t)(q0 + r) * 1536 + h * 64 + d0);
    }
    issueK(0);
    issueV(0);
    issueK(1);
    issueV(1);

    float Oa[8][4];
    #pragma unroll
    for (int i = 0; i < 8; i++)
        #pragma unroll
        for (int j = 0; j < 4; j++) Oa[i][j] = 0.0f;
    float mrow0 = NINF, mrow1 = NINF, lrow0 = 0.0f, lrow1 = 0.0f;

    int aRow = w * 16 + ((lane >> 3) & 1) * 8 + (lane & 7);
    int aSel = (lane >> 4) * 8;
    int bRowOff = (lane >> 4) * 8 + (lane & 7);
    int bSel = ((lane >> 3) & 1) * 8;
    int vKeyOff = ((lane >> 3) & 1) * 8 + (lane & 7);
    int vDSel = (lane >> 4);

    for (int kt = 0; kt < 8; kt++) {
        int cur = kt & 1;
        if (kt < 7) cpwait2(); else cpwait0();
        __syncthreads();

        uint32_t sK = sKb[cur], sV = sVb[cur];
        float sacc[16][4];
        #pragma unroll
        for (int nf = 0; nf < 16; nf++)
            #pragma unroll
            for (int j = 0; j < 4; j++) sacc[nf][j] = 0.0f;
        #pragma unroll
        for (int kk = 0; kk < 64; kk += 16) {
            uint32_t aq[4];
            ldsm4(aq, sQ + (uint32_t)(aRow * LQ + kk + aSel) * 2);
            #pragma unroll
            for (int nfp = 0; nfp < 8; nfp++) {
                uint32_t bq[4];
                ldsm4(bq, sK + (uint32_t)((nfp * 16 + bRowOff) * LQ + kk + bSel) * 2);
                mmaf16(sacc[2 * nfp], aq, bq[0], bq[1]);
                mmaf16(sacc[2 * nfp + 1], aq, bq[2], bq[3]);
            }
        }

        int r0l = w * 16 + g;
        uint32_t mwa[4], mwb[4];
        #pragma unroll
        for (int i = 0; i < 4; i++) {
            mwa[i] = mw[cur * 512 + r0l * 4 + i];
            mwb[i] = mw[cur * 512 + (r0l + 8) * 4 + i];
        }
        float mx0 = -3e38f, mx1 = -3e38f;
        #pragma unroll
        for (int nf = 0; nf < 16; nf++) {
            int c0 = nf * 8 + 2 * tg;
            uint32_t wa = mwa[c0 >> 5], wb = mwb[c0 >> 5];
            int shm = c0 & 31;
            float s00 = ((wa >> shm) & 1) ? NEGBIG : sacc[nf][0] * 0.125f;
            float s01 = ((wa >> (shm + 1)) & 1) ? NEGBIG : sacc[nf][1] * 0.125f;
            float s10 = ((wb >> shm) & 1) ? NEGBIG : sacc[nf][2] * 0.125f;
            float s11 = ((wb >> (shm + 1)) & 1) ? NEGBIG : sacc[nf][3] * 0.125f;
            sacc[nf][0] = s00; sacc[nf][1] = s01; sacc[nf][2] = s10; sacc[nf][3] = s11;
            mx0 = fmaxf(mx0, fmaxf(s00, s01));
            mx1 = fmaxf(mx1, fmaxf(s10, s11));
        }
        mx0 = fmaxf(mx0, __shfl_xor_sync(0xffffffffu, mx0, 1));
        mx0 = fmaxf(mx0, __shfl_xor_sync(0xffffffffu, mx0, 2));
        mx1 = fmaxf(mx1, __shfl_xor_sync(0xffffffffu, mx1, 1));
        mx1 = fmaxf(mx1, __shfl_xor_sync(0xffffffffu, mx1, 2));
        float mn0 = fmaxf(mrow0, mx0), mn1 = fmaxf(mrow1, mx1);
        float cf0 = __expf(mrow0 - mn0), cf1 = __expf(mrow1 - mn1);
        mrow0 = mn0; mrow1 = mn1;
        float rs0 = 0.0f, rs1 = 0.0f;
        #pragma unroll
        for (int nf = 0; nf < 16; nf++) {
            float p00 = __expf(sacc[nf][0] - mn0);
            float p01 = __expf(sacc[nf][1] - mn0);
            float p10 = __expf(sacc[nf][2] - mn1);
            float p11 = __expf(sacc[nf][3] - mn1);
            sacc[nf][0] = p00; sacc[nf][1] = p01; sacc[nf][2] = p10; sacc[nf][3] = p11;
            rs0 += p00 + p01; rs1 += p10 + p11;
        }
        rs0 += __shfl_xor_sync(0xffffffffu, rs0, 1);
        rs0 += __shfl_xor_sync(0xffffffffu, rs0, 2);
        rs1 += __shfl_xor_sync(0xffffffffu, rs1, 1);
        rs1 += __shfl_xor_sync(0xffffffffu, rs1, 2);
        lrow0 = lrow0 * cf0 + rs0;
        lrow1 = lrow1 * cf1 + rs1;
        #pragma unroll
        for (int df = 0; df < 8; df++) {
            Oa[df][0] *= cf0; Oa[df][1] *= cf0;
            Oa[df][2] *= cf1; Oa[df][3] *= cf1;
        }
        uint32_t pa[8][4];
        #pragma unroll
        for (int f = 0; f < 8; f++) {
            pa[f][0] = packh(sacc[2 * f][0], sacc[2 * f][1]);
            pa[f][1] = packh(sacc[2 * f][2], sacc[2 * f][3]);
            pa[f][2] = packh(sacc[2 * f + 1][0], sacc[2 * f + 1][1]);
            pa[f][3] = packh(sacc[2 * f + 1][2], sacc[2 * f + 1][3]);
        }

        #pragma unroll
        for (int f = 0; f < 8; f++) {
            #pragma unroll
            for (int q = 0; q < 4; q++) {
                uint32_t bv[4];
                ldsm4t(bv, sV + (uint32_t)((f * 16 + vKeyOff) * LQ + (vDSel + 2 * q) * 8) * 2);
                mmaf16(Oa[2 * q], pa[f], bv[0], bv[1]);
                mmaf16(Oa[2 * q + 1], pa[f], bv[2], bv[3]);
            }
        }
        __syncthreads();
        if (kt + 2 < 8) {
            issueK(kt + 2);
            issueV(kt + 2);
        }
    }

    float inv0 = 1.0f / lrow0, inv1 = 1.0f / lrow1;
    int orow = b * N_ + q0 + w * 16 + g;
    #pragma unroll
    for (int df = 0; df < 8; df++) {
        int col = h * 64 + df * 8 + 2 * tg;
        *(__half2*)(attn + (size_t)orow * 512 + col) =
            __floats2half2_rn(Oa[df][0] * inv0, Oa[df][1] * inv0);
        *(__half2*)(attn + (size_t)(orow + 8) * 512 + col) =
            __floats2half2_rn(Oa[df][2] * inv1, Oa[df][3] * inv1);
    }
}

// ---------------- att_topk + prune ----------------
__device__ __forceinline__ float blkmax(float v, float* red, int tid) {
    #pragma unroll
    for (int o = 16; o > 0; o >>= 1) v = fmaxf(v, __shfl_xor_sync(0xffffffffu, v, o));
    if ((tid & 31) == 0) red[tid >> 5] = v;
    __syncthreads();
    if (tid < 32) {
        float t = red[tid];
        #pragma unroll
        for (int o = 16; o > 0; o >>= 1) t = fmaxf(t, __shfl_xor_sync(0xffffffffu, t, o));
        if (tid == 0) red[0] = t;
    }
    __syncthreads();
    float r = red[0];
    __syncthreads();
    return r;
}
__device__ __forceinline__ float blksum(float v, float* red, int tid) {
    #pragma unroll
    for (int o = 16; o > 0; o >>= 1) v += __shfl_xor_sync(0xffffffffu, v, o);
    if ((tid & 31) == 0) red[tid >> 5] = v;
    __syncthreads();
    if (tid < 32) {
        float t = red[tid];
        #pragma unroll
        for (int o = 16; o > 0; o >>= 1) t += __shfl_xor_sync(0xffffffffu, t, o);
        if (tid == 0) red[0] = t;
    }
    __syncthreads();
    float r = red[0];
    __syncthreads();
    return r;
}
__global__ void __launch_bounds__(1024) topk0_kernel(const __half* __restrict__ qkv,
                                                     const float* __restrict__ mask,
                                                     float* __restrict__ topk) {
    int b = blockIdx.x, m = threadIdx.x;
    __shared__ float q0s[512];
    __shared__ float red[32];
    size_t rb = (size_t)b * N_ * 1536;
    if (m < 512) q0s[m] = __half2float(qkv[rb + m]);
    __syncthreads();
    const __half* krow = qkv + rb + (size_t)m * 1536 + 512;
    float s[8];
    #pragma unroll
    for (int h = 0; h < 8; h++) {
        float acc = 0.0f;
        #pragma unroll
        for (int j = 0; j < 64; j += 8) {
            uint4 kv = *(const uint4*)(krow + h * 64 + j);
            __half t[8]; *(uint4*)t = kv;
            #pragma unroll
            for (int i = 0; i < 8; i++) acc += q0s[h * 64 + j + i] * __half2float(t[i]);
        }
        s[h] = acc * 0.125f;
    }
    if (mask[(size_t)b * N_ * N_ + m] == 1.0f)
        #pragma unroll
        for (int h = 0; h < 8; h++) s[h] = NEGBIG;
    float out = 0.0f;
    #pragma unroll
    for (int h = 0; h < 8; h++) {
        float M = blkmax(s[h], red, m);
        float p = __expf(s[h] - M);
        float L = blksum(p, red, m);
        out += p / L;
    }
    topk[b * N_ + m] = out * 0.125f;
}

__global__ void __launch_bounds__(1024) prune_kernel(const float* __restrict__ topk,
                                                     float* __restrict__ out) {
    int b = blockIdx.x, m = threadIdx.x;
    __shared__ float key[N_];
    float km = (m == 0) ? NINF : topk[b * N_ + m];
    key[m] = km;
    __syncthreads();
    int rank = 0;
    for (int j = 0; j < N_; j++) {
        float kj = key[j];
        rank += (kj > km) || (kj == km && j < m);
    }
    if (rank >= 959 && rank < 1023) out[4194304 + b * 64 + (rank - 959)] = (float)m;
    if (m == 0) out[4194816 + b] = -1.0f;
    if (m < 16) out[4194824 + b * 16 + m] = 0.0f;
}

// ------- fp16 GEMM, cp.async 2-stage, tile 128x128 -------
// EPI: 0 = fp16 store; 2 = +bias+resid -> fp32; 3 = gelu(.+bias) -> fp16
template<int EPI>
__global__ void __launch_bounds__(256) gemm_k(
    const uint16_t* __restrict__ A, const uint16_t* __restrict__ Bm, void* __restrict__ Cp,
    int K, int lda, int ldb, int ldc,
    const float* __restrict__ bias, const float* __restrict__ resid)
{
    constexpr int LA = 40, LB = 136;
    __shared__ uint16_t As[2][128 * LA];
    __shared__ uint16_t Bs[2][32 * LB];
    int tid = threadIdx.x, warp = tid >> 5, lane = tid & 31;
    int g = lane >> 2, tg = lane & 3;
    int warpM = warp & 3, warpN = warp >> 2;
    int row0 = blockIdx.y * 128, col0 = blockIdx.x * 128;
    uint32_t sA = (uint32_t)__cvta_generic_to_shared(As);
    uint32_t sB = (uint32_t)__cvta_generic_to_shared(Bs);
    int koff = ((lane >> 3) & 1) * 8 + (lane & 7);
    int nsel = (lane >> 4) * 8;

    float acc[2][8][4];
    #pragma unroll
    for (int a = 0; a < 2; a++)
        #pragma unroll
        for (int b2 = 0; b2 < 8; b2++)
            #pragma unroll
            for (int c = 0; c < 4; c++) acc[a][b2][c] = 0.0f;

    auto issue = [&](int st, int k0) {
        #pragma unroll
        for (int it = 0, c = tid; it < 2; it++, c += 256) {
            int r = c >> 2, kc = (c & 3) * 8;
            cp16(sA + (st * 128 * LA + r * LA + kc) * 2,
                 A + (size_t)(row0 + r) * lda + k0 + kc);
        }
        #pragma unroll
        for (int it = 0, c = tid; it < 2; it++, c += 256) {
            int kk = c >> 4, nc = (c & 15) * 8;
            cp16(sB + (st * 32 * LB + kk * LB + nc) * 2,
                 Bm + (size_t)(k0 + kk) * ldb + col0 + nc);
        }
        cpcommit();
    };

    issue(0, 0);
    int nk = K / 32;
    for (int i = 0; i < nk; i++) {
        int st = i & 1;
        cpwait0();
        __syncthreads();
        if (i + 1 < nk) issue(st ^ 1, (i + 1) * 32);
        const uint16_t* Ab = As[st];
        uint32_t sBst = sB + st * 32 * LB * 2;
        #pragma unroll
        for (int kk = 0; kk < 32; kk += 16) {
            uint32_t af[2][4];
            #pragma unroll
            for (int mt = 0; mt < 2; mt++) {
                const uint16_t* p = &Ab[(warpM * 32 + mt * 16 + g) * LA + kk + 2 * tg];
                af[mt][0] = *(const uint32_t*)p;
                af[mt][1] = *(const uint32_t*)(p + 8 * LA);
                af[mt][2] = *(const uint32_t*)(p + 8);
                af[mt][3] = *(const uint32_t*)(p + 8 * LA + 8);
            }
            #pragma unroll
            for (int p2 = 0; p2 < 4; p2++) {
                uint32_t bq[4];
                ldsm4t(bq, sBst + (uint32_t)((kk + koff) * LB + warpN * 64 + p2 * 16 + nsel) * 2);
                #pragma unroll
                for (int mt = 0; mt < 2; mt++) {
                    mmaf16(acc[mt][2 * p2], af[mt], bq[0], bq[1]);
                    mmaf16(acc[mt][2 * p2 + 1], af[mt], bq[2], bq[3]);
                }
            }
        }
        __syncthreads();
    }
    #pragma unroll
    for (int mt = 0; mt < 2; mt++)
        #pragma unroll
        for (int nt = 0; nt < 8; nt++) {
            int r = row0 + warpM * 32 + mt * 16 + g;
            int cc = col0 + warpN * 64 + nt * 8 + 2 * tg;
            #pragma unroll
            for (int hf = 0; hf < 2; hf++) {
                int rr = r + hf * 8;
                float v0 = acc[mt][nt][hf * 2], v1 = acc[mt][nt][hf * 2 + 1];
                long idx = (long)rr * ldc + cc;
                if (EPI == 2) {
                    v0 += bias[cc] + resid[idx];
                    v1 += bias[cc + 1] + resid[idx + 1];
                    *(float2*)((float*)Cp + idx) = make_float2(v0, v1);
                } else {
                    if (EPI == 3) {
                        v0 += bias[cc]; v1 += bias[cc + 1];
                        v0 = 0.5f * v0 * (1.0f + erff(v0 * 0.70710678f));
                        v1 = 0.5f * v1 * (1.0f + erff(v1 * 0.70710678f));
                    }
                    *(uint32_t*)((uint16_t*)Cp + idx) = packh(v0, v1);
                }
            }
        }
}

// ---------------- host ----------------
template <typename T>
static T* symaddr(const T& sym) {
    void* p = nullptr;
    cudaGetSymbolAddress(&p, sym);
    return (T*)p;
}

extern "C" void kernel_launch(void* const* d_in, const int* in_sizes, int n_in,
                              void* d_out, int out_size) {
    const float* x    = (const float*)d_in[0];
    const float* mask = (const float*)d_in[1];
    const float* Wqkv = (const float*)d_in[2];
    const float* Wout = (const float*)d_in[3];
    const float* bout = (const float*)d_in[4];
    const float* ln1g = (const float*)d_in[5];
    const float* ln1b = (const float*)d_in[6];
    const float* ln2g = (const float*)d_in[7];
    const float* ln2b = (const float*)d_in[8];
    const float* W1   = (const float*)d_in[9];
    const float* b1   = (const float*)d_in[10];
    const float* W2   = (const float*)d_in[11];
    const float* b2   = (const float*)d_in[12];

    __half* h = (__half*)symaddr(g_h);
    __half* qkv = (__half*)symaddr(g_qkv);
    __half* attn = (__half*)symaddr(g_attn);
    float* x1 = (float*)symaddr(g_x1);
    __half* h2h = (__half*)symaddr(g_h2h);
    __half* ffh = (__half*)symaddr(g_ffh);
    float* tk = (float*)symaddr(g_topk);
    uint32_t* mb = (uint32_t*)symaddr(g_mbits);
    __half* wqkvh = (__half*)symaddr(g_Wqkvh);
    __half* wouth = (__half*)symaddr(g_Wouth);
    __half* w1h = (__half*)symaddr(g_W1h);
    __half* w2h = (__half*)symaddr(g_W2h);

    static cudaStream_t s1 = nullptr;
    static cudaEvent_t evA = nullptr, evB = nullptr, evC = nullptr, evD = nullptr, evE = nullptr;
    if (s1 == nullptr) {
        cudaStreamCreateWithFlags(&s1, cudaStreamNonBlocking);
        cudaEventCreateWithFlags(&evA, cudaEventDisableTiming);
        cudaEventCreateWithFlags(&evB, cudaEventDisableTiming);
        cudaEventCreateWithFlags(&evC, cudaEventDisableTiming);
        cudaEventCreateWithFlags(&evD, cudaEventDisableTiming);
        cudaEventCreateWithFlags(&evE, cudaEventDisableTiming);
        cudaFuncSetAttribute(flash_kernel, cudaFuncAttributeMaxDynamicSharedMemorySize, FL_SMEM);
    }

    // fork: maskbits + FF/Wout weight converts on s1, overlapping main chain
    cudaEventRecord(evA, 0);
    cudaStreamWaitEvent(s1, evA, 0);
    maskbits_kernel<<<B_ * N_ * N_ / 256, 256, 0, s1>>>(mask, mb);
    cudaEventRecord(evB, s1);                    // flash needs mbits
    cvth_kernel<<<(D_ * D_ + 255) / 256, 256, 0, s1>>>(Wout, wouth, D_ * D_);
    cvth_kernel<<<(D_ * MLP_ + 255) / 256, 256, 0, s1>>>(W1, w1h, D_ * MLP_);
    cvth_kernel<<<(MLP_ * D_ + 255) / 256, 256, 0, s1>>>(W2, w2h, MLP_ * D_);
    cudaEventRecord(evE, s1);                    // Wout GEMM needs these

    // main: Wqkv convert + ln1 + qkv GEMM
    cvth_kernel<<<(D_ * 3 * D_ + 255) / 256, 256>>>(Wqkv, wqkvh, D_ * 3 * D_);
    ln_kernel<<<ROWS_ / 8, 256>>>(x, ln1g, ln1b, h);
    gemm_k<0><<<dim3(12, 64), 256>>>(
        (const uint16_t*)h, (const uint16_t*)wqkvh, qkv, D_, D_, 3 * D_, 3 * D_,
        nullptr, nullptr);

    // fork: topk0 + prune on s1 (needs qkv), overlapping flash
    cudaEventRecord(evC, 0);
    cudaStreamWaitEvent(s1, evC, 0);
    topk0_kernel<<<B_, 1024, 0, s1>>>(qkv, mask, tk);
    prune_kernel<<<B_, 1024, 0, s1>>>(tk, (float*)d_out);
    cudaEventRecord(evD, s1);

    // main: flash (waits mbits), then Wout chain (waits weight converts)
    cudaStreamWaitEvent(0, evB, 0);
    flash_kernel<<<dim3(8, 64), 256, FL_SMEM>>>(qkv, mb, attn);
    cudaStreamWaitEvent(0, evE, 0);
    gemm_k<2><<<dim3(4, 64), 256>>>(
        (const uint16_t*)attn, (const uint16_t*)wouth, x1, D_, D_, D_, D_,
        bout, x);
    ln_kernel<<<ROWS_ / 8, 256>>>(x1, ln2g, ln2b, h2h);
    gemm_k<3><<<dim3(16, 64), 256>>>(
        (const uint16_t*)h2h, (const uint16_t*)w1h, ffh, D_, D_, MLP_, MLP_,
        b1, nullptr);
    gemm_k<2><<<dim3(4, 64), 256>>>(
        (const uint16_t*)ffh, (const uint16_t*)w2h, (float*)d_out, MLP_, MLP_, D_, D_,
        b2, x1);

    cudaStreamWaitEvent(0, evD, 0);
}